// round 12
// baseline (speedup 1.0000x reference)
#include <cuda_runtime.h>

#define D 64
#define NMAX 50000
#define EMAX 800000
#define MAXDEG 64

typedef unsigned long long u64;

// Scratch (device globals — no allocation allowed). 16B-aligned.
__device__ __align__(16) float g_y[NMAX * D];   // per-node MLP1 output
__device__ __align__(16) float g_a[NMAX * D];   // LN1(mean-agg) per node
__device__ int g_tab[NMAX * MAXDEG];            // bucket table: src rows per dst
__device__ int g_cnt[NMAX];                     // per-dst edge count (cursor)

// ---------------------------------------------------------------------------
// Packed fp32x2 helpers (sm_100+; FFMA2 unreachable from plain C++)
// ---------------------------------------------------------------------------
__device__ __forceinline__ u64 pack2(float lo, float hi) {
    u64 r; asm("mov.b64 %0, {%1, %2};" : "=l"(r) : "f"(lo), "f"(hi)); return r;
}
__device__ __forceinline__ u64 dup2(float s) { return pack2(s, s); }
__device__ __forceinline__ void unpack2(u64 v, float& lo, float& hi) {
    asm("mov.b64 {%0, %1}, %2;" : "=f"(lo), "=f"(hi) : "l"(v));
}
__device__ __forceinline__ u64 fma2(u64 a, u64 b, u64 c) {
    u64 d; asm("fma.rn.f32x2 %0, %1, %2, %3;" : "=l"(d) : "l"(a), "l"(b), "l"(c)); return d;
}
__device__ __forceinline__ u64 add2(u64 a, u64 b) {
    u64 d; asm("add.rn.f32x2 %0, %1, %2;" : "=l"(d) : "l"(a), "l"(b)); return d;
}
__device__ __forceinline__ u64 mul2(u64 a, u64 b) {
    u64 d; asm("mul.rn.f32x2 %0, %1, %2;" : "=l"(d) : "l"(a), "l"(b)); return d;
}
__device__ __forceinline__ u64 neg2(u64 a) { return a ^ 0x8000000080000000ULL; }
__device__ __forceinline__ float hsum2(u64 v) { float lo, hi; unpack2(v, lo, hi); return lo + hi; }

#define CPITCH 68
#define WPITCH 68
#define NT 256
#define TILE 64

// ---------------------------------------------------------------------------
// Register-tiled GEMM: block tile = 64 nodes x 64 outputs, 256 threads.
// Thread (ng = tid&31, og = tid>>5): nodes [ng*2,+2) x outputs [og*8,+8).
// og is warp-uniform -> W loads are broadcast LDS.128.
// ---------------------------------------------------------------------------
template <int K, bool INIT>
__device__ __forceinline__ void gemm_tile(const float* __restrict__ sC,
                                          const float* __restrict__ sW,
                                          int ng, int og, u64 acc[4][2]) {
    if (INIT) {
#pragma unroll
        for (int op = 0; op < 4; op++)
#pragma unroll
            for (int nn = 0; nn < 2; nn++) acc[op][nn] = 0ULL;
    }
    const float* cr = sC + ng * 2;
    const float* wr = sW + og * 8;
#pragma unroll 4
    for (int k = 0; k < K; k++) {
        float2 ca = *reinterpret_cast<const float2*>(cr + k * CPITCH);
        ulonglong2 w01 = *reinterpret_cast<const ulonglong2*>(wr + k * WPITCH);
        ulonglong2 w23 = *reinterpret_cast<const ulonglong2*>(wr + k * WPITCH + 4);
        float cv[2] = {ca.x, ca.y};
#pragma unroll
        for (int nn = 0; nn < 2; nn++) {
            u64 cd = dup2(cv[nn]);
            acc[0][nn] = fma2(w01.x, cd, acc[0][nn]);
            acc[1][nn] = fma2(w01.y, cd, acc[1][nn]);
            acc[2][nn] = fma2(w23.x, cd, acc[2][nn]);
            acc[3][nn] = fma2(w23.y, cd, acc[3][nn]);
        }
    }
}

// Stage activations [node][64] row-major -> sC[k][node], zero OOR nodes.
__device__ __forceinline__ void stage_C(const float* __restrict__ g, int base, int n,
                                        float* __restrict__ sC, int tid) {
    for (int idx = tid; idx < TILE * 16; idx += NT) {
        int node = idx >> 4, k4 = idx & 15;
        float4 v = make_float4(0.f, 0.f, 0.f, 0.f);
        if (base + node < n) v = reinterpret_cast<const float4*>(g + (size_t)(base + node) * D)[k4];
        sC[(4 * k4 + 0) * CPITCH + node] = v.x;
        sC[(4 * k4 + 1) * CPITCH + node] = v.y;
        sC[(4 * k4 + 2) * CPITCH + node] = v.z;
        sC[(4 * k4 + 3) * CPITCH + node] = v.w;
    }
}

// Stage weights w[j][k] (row stride RSTRIDE floats, 64 rows, 64 cols) -> sW[k][j].
template <int RSTRIDE>
__device__ __forceinline__ void stage_W(const float* __restrict__ w,
                                        float* __restrict__ sW, int tid) {
    for (int idx = tid; idx < 64 * 16; idx += NT) {
        int j = idx >> 4, k4 = idx & 15;
        float4 v = *reinterpret_cast<const float4*>(w + j * RSTRIDE + 4 * k4);
        sW[(4 * k4 + 0) * WPITCH + j] = v.x;
        sW[(4 * k4 + 1) * WPITCH + j] = v.y;
        sW[(4 * k4 + 2) * WPITCH + j] = v.z;
        sW[(4 * k4 + 3) * WPITCH + j] = v.w;
    }
}

// ReLU acc and write hidden tile sH[j][node] (k-major).
__device__ __forceinline__ void relu_to_smem(u64 acc[4][2], float* __restrict__ sH,
                                             int ng, int og) {
#pragma unroll
    for (int op = 0; op < 4; op++) {
        float l0, h0, l1, h1;
        unpack2(acc[op][0], l0, h0); unpack2(acc[op][1], l1, h1);
        float2 vlo = make_float2(fmaxf(l0, 0.f), fmaxf(l1, 0.f));
        float2 vhi = make_float2(fmaxf(h0, 0.f), fmaxf(h1, 0.f));
        *reinterpret_cast<float2*>(sH + (og * 8 + 2 * op) * CPITCH + ng * 2) = vlo;
        *reinterpret_cast<float2*>(sH + (og * 8 + 2 * op + 1) * CPITCH + ng * 2) = vhi;
    }
}

// Store acc tile to out[node][og*8..+8), guarded.
__device__ __forceinline__ void store_out(u64 acc[4][2], float* __restrict__ out,
                                          int base, int n, int ng, int og) {
#pragma unroll
    for (int nn = 0; nn < 2; nn++) {
        int node = base + ng * 2 + nn;
        if (node < n) {
            ulonglong2* p = reinterpret_cast<ulonglong2*>(out + (size_t)node * D + og * 8);
            ulonglong2 v0; v0.x = acc[0][nn]; v0.y = acc[1][nn];
            ulonglong2 v1; v1.x = acc[2][nn]; v1.y = acc[3][nn];
            p[0] = v0; p[1] = v1;
        }
    }
}

// ---------------------------------------------------------------------------
// MLP1: y = relu(x @ W1a^T) @ W1b^T  (per-node; 16x FLOP cut vs per-edge).
// Also zeroes g_cnt. smem: 2*64*68*4 = 34816 B.
// ---------------------------------------------------------------------------
__global__ __launch_bounds__(NT, 4) void mlp1_kernel(
    const float* __restrict__ x, const float* __restrict__ W1a,
    const float* __restrict__ W1b, int n)
{
    extern __shared__ __align__(16) float smem[];
    float* sC = smem;                    // [64][68]
    float* sW = smem + 64 * CPITCH;      // [64][68]
    int tid = threadIdx.x;
    int base = blockIdx.x * TILE;
    int ng = tid & 31, og = tid >> 5;

    stage_C(x, base, n, sC, tid);
    stage_W<64>(W1a, sW, tid);
    for (int i = blockIdx.x * NT + tid; i < n; i += gridDim.x * NT) g_cnt[i] = 0;
    __syncthreads();

    u64 acc[4][2];
    gemm_tile<64, true>(sC, sW, ng, og, acc);
    __syncthreads();

    relu_to_smem(acc, sC, ng, og);
    stage_W<64>(W1b, sW, tid);
    __syncthreads();

    gemm_tile<64, true>(sC, sW, ng, og, acc);
    store_out(acc, g_y, base, n, ng, og);
}

// ---------------------------------------------------------------------------
// Bucket fill: one thread per edge. edge_index is INT32 (jax downcasts int64).
// ---------------------------------------------------------------------------
__global__ void fill_kernel(const int* __restrict__ ei, int E, int n) {
    int e = blockIdx.x * blockDim.x + threadIdx.x;
    if (e >= E) return;
    int row = ei[e];
    int col = ei[E + e];
    if ((unsigned)row >= (unsigned)n || (unsigned)col >= (unsigned)n) return;
    int idx = atomicAdd(&g_cnt[col], 1);
    if (idx < MAXDEG) g_tab[(size_t)col * MAXDEG + idx] = row;
}

// ---------------------------------------------------------------------------
// Gather + LN1: one node per WARP (max parallelism; L2-BW-bound).
// lane owns features [2*lane, +2). a = LN1(sum(y[src]) / cnt) -> g_a.
// ---------------------------------------------------------------------------
__global__ __launch_bounds__(NT) void agg_kernel(
    const float* __restrict__ g1, const float* __restrict__ b1, int n)
{
    int t = blockIdx.x * NT + threadIdx.x;
    int node = t >> 5;
    int lane = t & 31;
    if (node >= n) return;

    int tc = g_cnt[node];
    int cnt = tc < MAXDEG ? tc : MAXDEG;
    const int* tp = g_tab + (size_t)node * MAXDEG;
    u64 s = 0ULL;
    for (int e = 0; e < cnt; e++) {
        int src = tp[e];   // warp-uniform broadcast load
        s = add2(s, *reinterpret_cast<const u64*>(g_y + (size_t)src * D + lane * 2));
    }
    float inv = 1.0f / (float)(tc > 1 ? tc : 1);
    s = mul2(s, dup2(inv));

    float p = hsum2(s);
#pragma unroll
    for (int o = 16; o; o >>= 1) p += __shfl_xor_sync(0xffffffffu, p, o);
    float m = p * (1.f / 64.f);
    u64 d = add2(s, dup2(-m));
    float vp = hsum2(mul2(d, d));
#pragma unroll
    for (int o = 16; o; o >>= 1) vp += __shfl_xor_sync(0xffffffffu, vp, o);
    float r = rsqrtf(vp * (1.f / 64.f) + 1e-5f);
    u64 a = fma2(mul2(d, dup2(r)),
                 reinterpret_cast<const u64*>(g1)[lane],
                 reinterpret_cast<const u64*>(b1)[lane]);
    *reinterpret_cast<u64*>(g_a + (size_t)node * D + lane * 2) = a;
}

// ---------------------------------------------------------------------------
// Fused epilogue, 256 threads, 64-node tile:
//  stage a (from g_a) -> sC; GEMM1-A: acc = C(a) @ W2a[:,64:128]^T
//  fx = LN2(x + (x-a)*w)  (4 thr/node, a reloaded from sC) -> sC
//  GEMM1-B: acc += C(fx) @ W2a[:,0:64]^T ; relu -> sC
//  GEMM2:   out  = H @ W2b^T
// smem: 2*64*68*4 + 2048 = 36864 B.
// ---------------------------------------------------------------------------
__global__ __launch_bounds__(NT, 4) void epilogue_kernel(
    const float* __restrict__ x,
    const float* __restrict__ wrep,
    const float* __restrict__ g2, const float* __restrict__ b2,
    const float* __restrict__ W2a, const float* __restrict__ W2b,
    float* __restrict__ out, int n)
{
    extern __shared__ __align__(16) float smem[];
    float* sC   = smem;                             // [64][68]
    float* sW   = smem + 64 * CPITCH;               // [64][68]
    float* sRed = smem + 128 * CPITCH;              // [2][256]
    int tid = threadIdx.x;
    int base = blockIdx.x * TILE;
    int ng = tid & 31, og = tid >> 5;
    int col = tid & 63;
    int h = tid >> 6;        // 0..3: feature quarter [h*16, +16)
    int nid = base + col;
    bool valid = nid < n;
    int safe = valid ? nid : 0;

    stage_C(g_a, base, n, sC, tid);          // sC = a (k-major)
    stage_W<128>(W2a + 64, sW, tid);         // W2a RIGHT half
    __syncthreads();

    u64 acc[4][2];
    gemm_tile<64, true>(sC, sW, ng, og, acc);   // acc = a-part
    __syncthreads();

    stage_W<128>(W2a, sW, tid);              // W2a LEFT half

    // ---- fx = LN2(x + (x - a)*w); 4 threads per node, 16 features each ----
    {
        const u64* pw  = reinterpret_cast<const u64*>(wrep) + h * 8;
        const u64* pg2 = reinterpret_cast<const u64*>(g2) + h * 8;
        const u64* pb2 = reinterpret_cast<const u64*>(b2) + h * 8;
        u64 f2[8];
        const ulonglong2* xp = reinterpret_cast<const ulonglong2*>(x + (size_t)safe * D + h * 16);
#pragma unroll
        for (int q = 0; q < 4; q++) {
            ulonglong2 v = xp[q];
            u64 vx = valid ? v.x : 0ULL, vy = valid ? v.y : 0ULL;
            u64 a0 = pack2(sC[(h * 16 + 4 * q) * CPITCH + col],
                           sC[(h * 16 + 4 * q + 1) * CPITCH + col]);
            u64 a1 = pack2(sC[(h * 16 + 4 * q + 2) * CPITCH + col],
                           sC[(h * 16 + 4 * q + 3) * CPITCH + col]);
            u64 d0 = add2(vx, neg2(a0));
            u64 d1 = add2(vy, neg2(a1));
            f2[2 * q]     = fma2(d0, pw[2 * q], vx);
            f2[2 * q + 1] = fma2(d1, pw[2 * q + 1], vy);
        }
        u64 s = 0ULL;
#pragma unroll
        for (int i = 0; i < 8; i++) s = add2(s, f2[i]);
        sRed[tid] = hsum2(s);
        __syncthreads();
        float m2 = ((sRed[col] + sRed[col + 64]) + (sRed[col + 128] + sRed[col + 192])) * (1.f / 64.f);
        u64 mneg = dup2(-m2);
        u64 vs = 0ULL;
#pragma unroll
        for (int i = 0; i < 8; i++) { u64 d = add2(f2[i], mneg); vs = fma2(d, d, vs); }
        sRed[256 + tid] = hsum2(vs);
        __syncthreads();
        float vv = (sRed[256 + col] + sRed[256 + col + 64]) + (sRed[256 + col + 128] + sRed[256 + col + 192]);
        float r2 = rsqrtf(vv * (1.f / 64.f) + 1e-5f);
        u64 r22 = dup2(r2);
#pragma unroll
        for (int i = 0; i < 8; i++) {
            u64 fv = fma2(mul2(add2(f2[i], mneg), r22), pg2[i], pb2[i]);
            float lo, hi; unpack2(fv, lo, hi);
            sC[(h * 16 + 2 * i) * CPITCH + col] = lo;        // own rows only:
            sC[(h * 16 + 2 * i + 1) * CPITCH + col] = hi;    // safe overwrite of a
        }
    }
    __syncthreads();   // sC(fx) + sW(W2a left) ready

    gemm_tile<64, false>(sC, sW, ng, og, acc);  // acc += fx-part
    __syncthreads();

    relu_to_smem(acc, sC, ng, og);              // hidden tile
    stage_W<64>(W2b, sW, tid);
    __syncthreads();

    gemm_tile<64, true>(sC, sW, ng, og, acc);
    store_out(acc, out, base, n, ng, og);
}

// ---------------------------------------------------------------------------
// Launch
// ---------------------------------------------------------------------------
extern "C" void kernel_launch(void* const* d_in, const int* in_sizes, int n_in,
                              void* d_out, int out_size) {
    const float* x   = (const float*)d_in[0];
    const int*   ei  = (const int*)d_in[1];      // int32 (jax downcasts int64)
    const float* W1a = (const float*)d_in[2];
    const float* W1b = (const float*)d_in[3];
    const float* g1  = (const float*)d_in[4];
    const float* b1  = (const float*)d_in[5];
    const float* w   = (const float*)d_in[6];
    const float* g2  = (const float*)d_in[7];
    const float* b2  = (const float*)d_in[8];
    const float* W2a = (const float*)d_in[9];
    const float* W2b = (const float*)d_in[10];
    float* out = (float*)d_out;

    int n = in_sizes[0] / D;
    int E = in_sizes[1] / 2;
    int blocks = (n + TILE - 1) / TILE;

    const int MLP1_SMEM = (128 * CPITCH) * 4;          // 34816 B
    const int EPI_SMEM  = (128 * CPITCH + 512) * 4;    // 36864 B
    cudaFuncSetAttribute(mlp1_kernel, cudaFuncAttributeMaxDynamicSharedMemorySize, MLP1_SMEM);
    cudaFuncSetAttribute(epilogue_kernel, cudaFuncAttributeMaxDynamicSharedMemorySize, EPI_SMEM);

    mlp1_kernel<<<blocks, NT, MLP1_SMEM>>>(x, W1a, W1b, n);
    fill_kernel<<<(E + 255) / 256, 256>>>(ei, E, n);
    agg_kernel<<<(n * 32 + NT - 1) / NT, NT>>>(g1, b1, n);
    epilogue_kernel<<<blocks, NT, EPI_SMEM>>>(x, w, g2, b2, W2a, W2b, out, n);
}

// round 13
// speedup vs baseline: 1.1808x; 1.1808x over previous
#include <cuda_runtime.h>

#define D 64
#define NMAX 50000
#define EMAX 800000
#define MAXDEG 64

typedef unsigned long long u64;

// Scratch (device globals — no allocation allowed). 16B-aligned.
__device__ __align__(16) float g_y[NMAX * D];   // per-node MLP1 output
__device__ __align__(16) float g_a[NMAX * D];   // LN1(mean-agg) per node
__device__ int g_tab[NMAX * MAXDEG];            // bucket table: src rows per dst
__device__ int g_cnt[NMAX];                     // per-dst edge count (cursor)

// ---------------------------------------------------------------------------
// Packed fp32x2 helpers (sm_100+; FFMA2 unreachable from plain C++)
// ---------------------------------------------------------------------------
__device__ __forceinline__ u64 pack2(float lo, float hi) {
    u64 r; asm("mov.b64 %0, {%1, %2};" : "=l"(r) : "f"(lo), "f"(hi)); return r;
}
__device__ __forceinline__ u64 dup2(float s) { return pack2(s, s); }
__device__ __forceinline__ void unpack2(u64 v, float& lo, float& hi) {
    asm("mov.b64 {%0, %1}, %2;" : "=f"(lo), "=f"(hi) : "l"(v));
}
__device__ __forceinline__ u64 fma2(u64 a, u64 b, u64 c) {
    u64 d; asm("fma.rn.f32x2 %0, %1, %2, %3;" : "=l"(d) : "l"(a), "l"(b), "l"(c)); return d;
}
__device__ __forceinline__ u64 add2(u64 a, u64 b) {
    u64 d; asm("add.rn.f32x2 %0, %1, %2;" : "=l"(d) : "l"(a), "l"(b)); return d;
}
__device__ __forceinline__ u64 mul2(u64 a, u64 b) {
    u64 d; asm("mul.rn.f32x2 %0, %1, %2;" : "=l"(d) : "l"(a), "l"(b)); return d;
}
__device__ __forceinline__ u64 neg2(u64 a) { return a ^ 0x8000000080000000ULL; }
__device__ __forceinline__ float hsum2(u64 v) { float lo, hi; unpack2(v, lo, hi); return lo + hi; }

#define CPITCH 132
#define WPITCH 68
#define NT 256

// ---------------------------------------------------------------------------
// Register-tiled GEMM: block tile = 128 nodes x 64 outputs, 256 threads.
// Thread (ng = tid&31, og = tid>>5): nodes [ng*4,+4) x outputs [og*8,+8).
// og is warp-uniform -> W loads are broadcast LDS.128. (R10 configuration —
// best LDS-wavefronts-per-FMA ratio measured so far.)
// ---------------------------------------------------------------------------
template <int K, bool INIT>
__device__ __forceinline__ void gemm_tile(const float* __restrict__ sC,
                                          const float* __restrict__ sW,
                                          int ng, int og, u64 acc[4][4]) {
    if (INIT) {
#pragma unroll
        for (int op = 0; op < 4; op++)
#pragma unroll
            for (int nn = 0; nn < 4; nn++) acc[op][nn] = 0ULL;
    }
    const float* cr = sC + ng * 4;
    const float* wr = sW + og * 8;
#pragma unroll 4
    for (int k = 0; k < K; k++) {
        float4 ca = *reinterpret_cast<const float4*>(cr + k * CPITCH);
        ulonglong2 w01 = *reinterpret_cast<const ulonglong2*>(wr + k * WPITCH);
        ulonglong2 w23 = *reinterpret_cast<const ulonglong2*>(wr + k * WPITCH + 4);
        float cv[4] = {ca.x, ca.y, ca.z, ca.w};
#pragma unroll
        for (int nn = 0; nn < 4; nn++) {
            u64 cd = dup2(cv[nn]);
            acc[0][nn] = fma2(w01.x, cd, acc[0][nn]);
            acc[1][nn] = fma2(w01.y, cd, acc[1][nn]);
            acc[2][nn] = fma2(w23.x, cd, acc[2][nn]);
            acc[3][nn] = fma2(w23.y, cd, acc[3][nn]);
        }
    }
}

// Stage activations [node][K] row-major -> sC[k][node], zero OOR nodes.
template <int K>
__device__ __forceinline__ void stage_C(const float* __restrict__ g, int base, int n,
                                        float* __restrict__ sC, int tid) {
    const int K4 = K / 4;
    for (int idx = tid; idx < 128 * K4; idx += NT) {
        int node = idx / K4, k4 = idx % K4;
        float4 v = make_float4(0.f, 0.f, 0.f, 0.f);
        if (base + node < n) v = reinterpret_cast<const float4*>(g + (size_t)(base + node) * K)[k4];
        sC[(4 * k4 + 0) * CPITCH + node] = v.x;
        sC[(4 * k4 + 1) * CPITCH + node] = v.y;
        sC[(4 * k4 + 2) * CPITCH + node] = v.z;
        sC[(4 * k4 + 3) * CPITCH + node] = v.w;
    }
}

// Stage weights w[j][k] (row stride RSTRIDE floats, 64 rows, K cols) -> sW[k][j].
template <int K, int RSTRIDE>
__device__ __forceinline__ void stage_W(const float* __restrict__ w,
                                        float* __restrict__ sW, int tid) {
    const int K4 = K / 4;
    for (int idx = tid; idx < 64 * K4; idx += NT) {
        int j = idx / K4, k4 = idx % K4;
        float4 v = *reinterpret_cast<const float4*>(w + j * RSTRIDE + 4 * k4);
        sW[(4 * k4 + 0) * WPITCH + j] = v.x;
        sW[(4 * k4 + 1) * WPITCH + j] = v.y;
        sW[(4 * k4 + 2) * WPITCH + j] = v.z;
        sW[(4 * k4 + 3) * WPITCH + j] = v.w;
    }
}

// ReLU acc and write hidden tile sH[j][node] (k-major), STS.128 conflict-free.
__device__ __forceinline__ void relu_to_smem(u64 acc[4][4], float* __restrict__ sH,
                                             int ng, int og) {
#pragma unroll
    for (int op = 0; op < 4; op++) {
        float l0, h0, l1, h1, l2, h2, l3, h3;
        unpack2(acc[op][0], l0, h0); unpack2(acc[op][1], l1, h1);
        unpack2(acc[op][2], l2, h2); unpack2(acc[op][3], l3, h3);
        float4 vlo = make_float4(fmaxf(l0, 0.f), fmaxf(l1, 0.f), fmaxf(l2, 0.f), fmaxf(l3, 0.f));
        float4 vhi = make_float4(fmaxf(h0, 0.f), fmaxf(h1, 0.f), fmaxf(h2, 0.f), fmaxf(h3, 0.f));
        *reinterpret_cast<float4*>(sH + (og * 8 + 2 * op) * CPITCH + ng * 4) = vlo;
        *reinterpret_cast<float4*>(sH + (og * 8 + 2 * op + 1) * CPITCH + ng * 4) = vhi;
    }
}

// Store acc tile to out[node][og*8..+8), guarded.
__device__ __forceinline__ void store_out(u64 acc[4][4], float* __restrict__ out,
                                          int base, int n, int ng, int og) {
#pragma unroll
    for (int nn = 0; nn < 4; nn++) {
        int node = base + ng * 4 + nn;
        if (node < n) {
            ulonglong2* p = reinterpret_cast<ulonglong2*>(out + (size_t)node * D + og * 8);
            ulonglong2 v0; v0.x = acc[0][nn]; v0.y = acc[1][nn];
            ulonglong2 v1; v1.x = acc[2][nn]; v1.y = acc[3][nn];
            p[0] = v0; p[1] = v1;
        }
    }
}

// ---------------------------------------------------------------------------
// MLP1: y = relu(x @ W1a^T) @ W1b^T  (per-node; 16x FLOP cut vs per-edge).
// Also zeroes g_cnt. smem: 64*132 + 64*68 = 51200 B -> 3 CTAs/SM.
// (Exact R10 configuration — best measured.)
// ---------------------------------------------------------------------------
__global__ __launch_bounds__(NT, 3) void mlp1_kernel(
    const float* __restrict__ x, const float* __restrict__ W1a,
    const float* __restrict__ W1b, int n)
{
    extern __shared__ __align__(16) float smem[];
    float* sC = smem;                  // [64][132]
    float* sW = smem + 64 * CPITCH;    // [64][68]
    int tid = threadIdx.x;
    int base = blockIdx.x * 128;
    int ng = tid & 31, og = tid >> 5;

    stage_C<64>(x, base, n, sC, tid);
    stage_W<64, 64>(W1a, sW, tid);
    for (int i = blockIdx.x * NT + tid; i < n; i += gridDim.x * NT) g_cnt[i] = 0;
    __syncthreads();

    u64 acc[4][4];
    gemm_tile<64, true>(sC, sW, ng, og, acc);
    __syncthreads();

    relu_to_smem(acc, sC, ng, og);
    stage_W<64, 64>(W1b, sW, tid);
    __syncthreads();

    gemm_tile<64, true>(sC, sW, ng, og, acc);
    store_out(acc, g_y, base, n, ng, og);
}

// ---------------------------------------------------------------------------
// Bucket fill: one thread per edge. edge_index is INT32 (jax downcasts int64).
// ---------------------------------------------------------------------------
__global__ void fill_kernel(const int* __restrict__ ei, int E, int n) {
    int e = blockIdx.x * blockDim.x + threadIdx.x;
    if (e >= E) return;
    int row = ei[e];
    int col = ei[E + e];
    if ((unsigned)row >= (unsigned)n || (unsigned)col >= (unsigned)n) return;
    int idx = atomicAdd(&g_cnt[col], 1);
    if (idx < MAXDEG) g_tab[(size_t)col * MAXDEG + idx] = row;
}

// ---------------------------------------------------------------------------
// Gather + LN1: one node per WARP, 4-way partial sums so 4 independent L2
// gather loads are in flight (MLP=4). lane owns features [2*lane, +2).
// a = LN1(sum(y[src]) / cnt) -> g_a.
// ---------------------------------------------------------------------------
__global__ __launch_bounds__(NT) void agg_kernel(
    const float* __restrict__ g1, const float* __restrict__ b1, int n)
{
    int t = blockIdx.x * NT + threadIdx.x;
    int node = t >> 5;
    int lane = t & 31;
    if (node >= n) return;

    int tc = g_cnt[node];
    int cnt = tc < MAXDEG ? tc : MAXDEG;
    const int* tp = g_tab + (size_t)node * MAXDEG;
    const char* yb = reinterpret_cast<const char*>(g_y) + lane * 8;

    u64 s0 = 0ULL, s1 = 0ULL, s2 = 0ULL, s3 = 0ULL;
    int e = 0;
    for (; e + 4 <= cnt; e += 4) {
        int i0 = tp[e], i1 = tp[e + 1], i2 = tp[e + 2], i3 = tp[e + 3];
        s0 = add2(s0, *reinterpret_cast<const u64*>(yb + (size_t)i0 * 256));
        s1 = add2(s1, *reinterpret_cast<const u64*>(yb + (size_t)i1 * 256));
        s2 = add2(s2, *reinterpret_cast<const u64*>(yb + (size_t)i2 * 256));
        s3 = add2(s3, *reinterpret_cast<const u64*>(yb + (size_t)i3 * 256));
    }
    for (; e < cnt; e++)
        s0 = add2(s0, *reinterpret_cast<const u64*>(yb + (size_t)tp[e] * 256));
    u64 s = add2(add2(s0, s1), add2(s2, s3));

    float inv = 1.0f / (float)(tc > 1 ? tc : 1);
    s = mul2(s, dup2(inv));

    float p = hsum2(s);
#pragma unroll
    for (int o = 16; o; o >>= 1) p += __shfl_xor_sync(0xffffffffu, p, o);
    float m = p * (1.f / 64.f);
    u64 d = add2(s, dup2(-m));
    float vp = hsum2(mul2(d, d));
#pragma unroll
    for (int o = 16; o; o >>= 1) vp += __shfl_xor_sync(0xffffffffu, vp, o);
    float r = rsqrtf(vp * (1.f / 64.f) + 1e-5f);
    u64 a = fma2(mul2(d, dup2(r)),
                 reinterpret_cast<const u64*>(g1)[lane],
                 reinterpret_cast<const u64*>(b1)[lane]);
    *reinterpret_cast<u64*>(g_a + (size_t)node * D + lane * 2) = a;
}

// ---------------------------------------------------------------------------
// Fused epilogue (R10 skeleton, gather phase replaced by staging g_a):
//  stage a (from g_a) -> sC; GEMM1-A: acc = C(a) @ W2a[:,64:128]^T
//  fx = LN2(x + (x-a)*w)  (2 thr/node, a reloaded from sC) -> sC
//  GEMM1-B: acc += C(fx) @ W2a[:,0:64]^T ; relu -> sC
//  GEMM2:   out  = H @ W2b^T
// smem: 64*132 + 64*68 + 1024 = 55296 B -> 3 CTAs/SM.
// ---------------------------------------------------------------------------
__global__ __launch_bounds__(NT, 3) void epilogue_kernel(
    const float* __restrict__ x,
    const float* __restrict__ wrep,
    const float* __restrict__ g2, const float* __restrict__ b2,
    const float* __restrict__ W2a, const float* __restrict__ W2b,
    float* __restrict__ out, int n)
{
    extern __shared__ __align__(16) float smem[];
    float* sC   = smem;                             // [64][132]
    float* sW   = smem + 64 * CPITCH;               // [64][68]
    float* sRed = smem + 64 * CPITCH + 64 * WPITCH; // [4][256]
    int tid = threadIdx.x;
    int base = blockIdx.x * 128;
    int ng = tid & 31, og = tid >> 5;
    int col = tid & 127;
    int h = tid >> 7;
    int nid = base + col;
    bool valid = nid < n;
    int safe = valid ? nid : 0;

    stage_C<64>(g_a, base, n, sC, tid);      // sC = a (k-major)
    stage_W<64, 128>(W2a + 64, sW, tid);     // W2a RIGHT half
    __syncthreads();

    u64 acc[4][4];
    gemm_tile<64, true>(sC, sW, ng, og, acc);   // acc = a-part
    __syncthreads();

    stage_W<64, 128>(W2a, sW, tid);          // W2a LEFT half

    // ---- fx = LN2(x + (x - a)*w); a reloaded from sC (2 thr/node) ----
    {
        const u64* pw  = reinterpret_cast<const u64*>(wrep) + h * 16;
        const u64* pg2 = reinterpret_cast<const u64*>(g2) + h * 16;
        const u64* pb2 = reinterpret_cast<const u64*>(b2) + h * 16;
        u64 f2[16];
        const ulonglong2* xp = reinterpret_cast<const ulonglong2*>(x + (size_t)safe * D + h * 32);
#pragma unroll
        for (int q = 0; q < 8; q++) {
            ulonglong2 v = xp[q];
            u64 vx = valid ? v.x : 0ULL, vy = valid ? v.y : 0ULL;
            u64 a0 = pack2(sC[(h * 32 + 4 * q) * CPITCH + col],
                           sC[(h * 32 + 4 * q + 1) * CPITCH + col]);
            u64 a1 = pack2(sC[(h * 32 + 4 * q + 2) * CPITCH + col],
                           sC[(h * 32 + 4 * q + 3) * CPITCH + col]);
            u64 d0 = add2(vx, neg2(a0));
            u64 d1 = add2(vy, neg2(a1));
            f2[2 * q]     = fma2(d0, pw[2 * q], vx);
            f2[2 * q + 1] = fma2(d1, pw[2 * q + 1], vy);
        }
        u64 s = 0ULL;
#pragma unroll
        for (int i = 0; i < 16; i++) s = add2(s, f2[i]);
        sRed[tid] = hsum2(s);
        __syncthreads();   // also orders all sC(a) reads before sC(fx) writes
        float m2 = (sRed[tid] + sRed[tid ^ 128]) * (1.f / 64.f);
        u64 mneg = dup2(-m2);
        u64 vs = 0ULL;
#pragma unroll
        for (int i = 0; i < 16; i++) { u64 d = add2(f2[i], mneg); vs = fma2(d, d, vs); }
        sRed[256 + tid] = hsum2(vs);
        __syncthreads();
        float r2 = rsqrtf((sRed[256 + tid] + sRed[256 + (tid ^ 128)]) * (1.f / 64.f) + 1e-5f);
        u64 r22 = dup2(r2);
#pragma unroll
        for (int i = 0; i < 16; i++) {
            u64 fv = fma2(mul2(add2(f2[i], mneg), r22), pg2[i], pb2[i]);
            float lo, hi; unpack2(fv, lo, hi);
            sC[(h * 32 + 2 * i) * CPITCH + col] = lo;
            sC[(h * 32 + 2 * i + 1) * CPITCH + col] = hi;
        }
    }
    __syncthreads();   // sC(fx) + sW(W2a left) ready

    gemm_tile<64, false>(sC, sW, ng, og, acc);  // acc += fx-part
    __syncthreads();

    relu_to_smem(acc, sC, ng, og);              // hidden tile
    stage_W<64, 64>(W2b, sW, tid);
    __syncthreads();

    gemm_tile<64, true>(sC, sW, ng, og, acc);
    store_out(acc, out, base, n, ng, og);
}

// ---------------------------------------------------------------------------
// Launch
// ---------------------------------------------------------------------------
extern "C" void kernel_launch(void* const* d_in, const int* in_sizes, int n_in,
                              void* d_out, int out_size) {
    const float* x   = (const float*)d_in[0];
    const int*   ei  = (const int*)d_in[1];      // int32 (jax downcasts int64)
    const float* W1a = (const float*)d_in[2];
    const float* W1b = (const float*)d_in[3];
    const float* g1  = (const float*)d_in[4];
    const float* b1  = (const float*)d_in[5];
    const float* w   = (const float*)d_in[6];
    const float* g2  = (const float*)d_in[7];
    const float* b2  = (const float*)d_in[8];
    const float* W2a = (const float*)d_in[9];
    const float* W2b = (const float*)d_in[10];
    float* out = (float*)d_out;

    int n = in_sizes[0] / D;
    int E = in_sizes[1] / 2;
    int blocks = (n + 127) / 128;

    const int MLP1_SMEM = (64 * CPITCH + 64 * WPITCH) * 4;            // 51200 B
    const int EPI_SMEM  = (64 * CPITCH + 64 * WPITCH + 1024) * 4;     // 55296 B
    cudaFuncSetAttribute(mlp1_kernel, cudaFuncAttributeMaxDynamicSharedMemorySize, MLP1_SMEM);
    cudaFuncSetAttribute(epilogue_kernel, cudaFuncAttributeMaxDynamicSharedMemorySize, EPI_SMEM);

    mlp1_kernel<<<blocks, NT, MLP1_SMEM>>>(x, W1a, W1b, n);
    fill_kernel<<<(E + 255) / 256, 256>>>(ei, E, n);
    agg_kernel<<<(n * 32 + NT - 1) / NT, NT>>>(g1, b1, n);
    epilogue_kernel<<<blocks, NT, EPI_SMEM>>>(x, w, g2, b2, W2a, W2b, out, n);
}

// round 14
// speedup vs baseline: 1.2346x; 1.0456x over previous
#include <cuda_runtime.h>

#define D 64
#define NMAX 50000
#define EMAX 800000
#define MAXDEG 64

typedef unsigned long long u64;
typedef unsigned int u32;

// Scratch (device globals — no allocation allowed). 16B-aligned.
__device__ __align__(16) float g_y[NMAX * D];   // per-node MLP1 output
__device__ __align__(16) float g_a[NMAX * D];   // LN1(mean-agg) per node
__device__ int g_tab[NMAX * MAXDEG];            // bucket table: src rows per dst
__device__ int g_cnt[NMAX];                     // per-dst edge count (cursor)

// ---------------------------------------------------------------------------
// Packed fp32x2 helpers (for agg kernel + LN phases)
// ---------------------------------------------------------------------------
__device__ __forceinline__ u64 pack2(float lo, float hi) {
    u64 r; asm("mov.b64 %0, {%1, %2};" : "=l"(r) : "f"(lo), "f"(hi)); return r;
}
__device__ __forceinline__ u64 dup2(float s) { return pack2(s, s); }
__device__ __forceinline__ void unpack2(u64 v, float& lo, float& hi) {
    asm("mov.b64 {%0, %1}, %2;" : "=f"(lo), "=f"(hi) : "l"(v));
}
__device__ __forceinline__ u64 fma2(u64 a, u64 b, u64 c) {
    u64 d; asm("fma.rn.f32x2 %0, %1, %2, %3;" : "=l"(d) : "l"(a), "l"(b), "l"(c)); return d;
}
__device__ __forceinline__ u64 add2(u64 a, u64 b) {
    u64 d; asm("add.rn.f32x2 %0, %1, %2;" : "=l"(d) : "l"(a), "l"(b)); return d;
}
__device__ __forceinline__ u64 mul2(u64 a, u64 b) {
    u64 d; asm("mul.rn.f32x2 %0, %1, %2;" : "=l"(d) : "l"(a), "l"(b)); return d;
}
__device__ __forceinline__ u64 neg2(u64 a) { return a ^ 0x8000000080000000ULL; }
__device__ __forceinline__ float hsum2(u64 v) { float lo, hi; unpack2(v, lo, hi); return lo + hi; }

// tf32 helpers
__device__ __forceinline__ u32 tf32_rna(float f) {
    u32 r; asm("cvt.rna.tf32.f32 %0, %1;" : "=r"(r) : "f"(f)); return r;
}
__device__ __forceinline__ void split_tf32(float f, float& hi, float& lo) {
    u32 h = tf32_rna(f);
    hi = __uint_as_float(h);
    lo = __uint_as_float(tf32_rna(f - hi));
}

#define CPITCH 136   // = 8 mod 32 -> frag-load banks 8*lc+lr: perfect permutation
#define WPITCH 72    // = 8 mod 32 -> same
#define NT 256

// m16n8k8 tf32 mma, accumulate in place.
__device__ __forceinline__ void mma8(float d[4], const u32 a[4], const u32 b[2]) {
    asm("mma.sync.aligned.m16n8k8.row.col.f32.tf32.tf32.f32 "
        "{%0,%1,%2,%3}, {%4,%5,%6,%7}, {%8,%9}, {%0,%1,%2,%3};"
        : "+f"(d[0]), "+f"(d[1]), "+f"(d[2]), "+f"(d[3])
        : "r"(a[0]), "r"(a[1]), "r"(a[2]), "r"(a[3]), "r"(b[0]), "r"(b[1]));
}

// ---------------------------------------------------------------------------
// 3xTF32 GEMM: block tile 128m x 64n, K = KCHUNKS*8. 8 warps: mb=(wid&3)*32,
// nb=(wid>>2)*32; warp tile 32x32 = 2 m-tiles x 4 n-tiles. sA: [k][m] pitch
// CPITCH (hi/lo), sW: [k][n] pitch WPITCH (hi/lo). D[t][u][4] fp32 accs.
// ---------------------------------------------------------------------------
template <int KCHUNKS, bool INIT>
__device__ __forceinline__ void mma_gemm(
    const float* __restrict__ sAh, const float* __restrict__ sAl,
    const float* __restrict__ sWh, const float* __restrict__ sWl,
    int mb, int nb, int lane, float Dt[2][4][4])
{
    if (INIT) {
#pragma unroll
        for (int t = 0; t < 2; t++)
#pragma unroll
            for (int u = 0; u < 4; u++)
#pragma unroll
                for (int e = 0; e < 4; e++) Dt[t][u][e] = 0.f;
    }
    int lr = lane >> 2, lc = lane & 3;
#pragma unroll 2
    for (int kc = 0; kc < KCHUNKS; kc++) {
        int k0 = kc * 8 + lc;
        u32 Ah[2][4], Al[2][4], Bh[4][2], Bl[4][2];
#pragma unroll
        for (int t = 0; t < 2; t++) {
            int m = mb + t * 16 + lr;
            const float* p0h = sAh + k0 * CPITCH + m;
            const float* p1h = sAh + (k0 + 4) * CPITCH + m;
            Ah[t][0] = __float_as_uint(p0h[0]);
            Ah[t][1] = __float_as_uint(p0h[8]);
            Ah[t][2] = __float_as_uint(p1h[0]);
            Ah[t][3] = __float_as_uint(p1h[8]);
            const float* p0l = sAl + k0 * CPITCH + m;
            const float* p1l = sAl + (k0 + 4) * CPITCH + m;
            Al[t][0] = __float_as_uint(p0l[0]);
            Al[t][1] = __float_as_uint(p0l[8]);
            Al[t][2] = __float_as_uint(p1l[0]);
            Al[t][3] = __float_as_uint(p1l[8]);
        }
#pragma unroll
        for (int u = 0; u < 4; u++) {
            int nn = nb + u * 8 + lr;
            Bh[u][0] = __float_as_uint(sWh[k0 * WPITCH + nn]);
            Bh[u][1] = __float_as_uint(sWh[(k0 + 4) * WPITCH + nn]);
            Bl[u][0] = __float_as_uint(sWl[k0 * WPITCH + nn]);
            Bl[u][1] = __float_as_uint(sWl[(k0 + 4) * WPITCH + nn]);
        }
#pragma unroll
        for (int t = 0; t < 2; t++)
#pragma unroll
            for (int u = 0; u < 4; u++) {
                mma8(Dt[t][u], Ah[t], Bh[u]);
                mma8(Dt[t][u], Ah[t], Bl[u]);
                mma8(Dt[t][u], Al[t], Bh[u]);
            }
    }
}

// Stage activations [node][64] -> sA hi/lo [k][node]. Node-major indexing so
// STS banks are distinct (pitch 136 would alias on k-major indexing).
__device__ __forceinline__ void stage_C_split(const float* __restrict__ g, int base, int n,
                                              float* __restrict__ sAh, float* __restrict__ sAl,
                                              int tid) {
    for (int idx = tid; idx < 128 * 16; idx += NT) {
        int k4 = idx >> 7, node = idx & 127;
        float4 v = make_float4(0.f, 0.f, 0.f, 0.f);
        if (base + node < n) v = reinterpret_cast<const float4*>(g + (size_t)(base + node) * D)[k4];
        float fv[4] = {v.x, v.y, v.z, v.w};
#pragma unroll
        for (int i = 0; i < 4; i++) {
            float hi, lo; split_tf32(fv[i], hi, lo);
            sAh[(4 * k4 + i) * CPITCH + node] = hi;
            sAl[(4 * k4 + i) * CPITCH + node] = lo;
        }
    }
}

// Stage weights w[j][k] (64 rows, row stride RSTRIDE) -> sW hi/lo [k][j].
template <int RSTRIDE>
__device__ __forceinline__ void stage_W_split(const float* __restrict__ w,
                                              float* __restrict__ sWh, float* __restrict__ sWl,
                                              int tid) {
    for (int idx = tid; idx < 64 * 16; idx += NT) {
        int k4 = idx >> 6, j = idx & 63;
        float4 v = *reinterpret_cast<const float4*>(w + j * RSTRIDE + 4 * k4);
        float fv[4] = {v.x, v.y, v.z, v.w};
#pragma unroll
        for (int i = 0; i < 4; i++) {
            float hi, lo; split_tf32(fv[i], hi, lo);
            sWh[(4 * k4 + i) * WPITCH + j] = hi;
            sWl[(4 * k4 + i) * WPITCH + j] = lo;
        }
    }
}

// ReLU the accs and write hidden tile (split) back as next GEMM's A: sA[j][m].
__device__ __forceinline__ void relu_split(float Dt[2][4][4],
                                           float* __restrict__ sAh, float* __restrict__ sAl,
                                           int mb, int nb, int lane) {
    int lr = lane >> 2, lc = lane & 3;
#pragma unroll
    for (int t = 0; t < 2; t++)
#pragma unroll
        for (int u = 0; u < 4; u++) {
            int m0 = mb + t * 16 + lr;
            int n0 = nb + u * 8 + 2 * lc;
            float e[4] = {Dt[t][u][0], Dt[t][u][1], Dt[t][u][2], Dt[t][u][3]};
            int mm[4] = {m0, m0, m0 + 8, m0 + 8};
            int nn[4] = {n0, n0 + 1, n0, n0 + 1};
#pragma unroll
            for (int q = 0; q < 4; q++) {
                float f = fmaxf(e[q], 0.f);
                float hi, lo; split_tf32(f, hi, lo);
                sAh[nn[q] * CPITCH + mm[q]] = hi;
                sAl[nn[q] * CPITCH + mm[q]] = lo;
            }
        }
}

// Store accs to out[node][n], guarded; paired 8B stores.
__device__ __forceinline__ void store_frag(float Dt[2][4][4], float* __restrict__ out,
                                           int base, int n, int mb, int nb, int lane) {
    int lr = lane >> 2, lc = lane & 3;
#pragma unroll
    for (int t = 0; t < 2; t++) {
        int m0 = mb + t * 16 + lr;
#pragma unroll
        for (int u = 0; u < 4; u++) {
            int n0 = nb + u * 8 + 2 * lc;
            int node0 = base + m0;
            int node1 = base + m0 + 8;
            if (node0 < n)
                *reinterpret_cast<u64*>(out + (size_t)node0 * D + n0) = pack2(Dt[t][u][0], Dt[t][u][1]);
            if (node1 < n)
                *reinterpret_cast<u64*>(out + (size_t)node1 * D + n0) = pack2(Dt[t][u][2], Dt[t][u][3]);
        }
    }
}

// ---------------------------------------------------------------------------
// MLP1: y = relu(x @ W1a^T) @ W1b^T  (per-node; 16x FLOP cut vs per-edge).
// 3xTF32 tensor-core GEMMs. Also zeroes g_cnt.
// smem: 2*64*136 + 2*64*72 = 26624 floats = 106496 B -> 2 CTAs/SM.
// ---------------------------------------------------------------------------
__global__ __launch_bounds__(NT, 2) void mlp1_kernel(
    const float* __restrict__ x, const float* __restrict__ W1a,
    const float* __restrict__ W1b, int n)
{
    extern __shared__ __align__(16) float smem[];
    float* sAh = smem;                       // [64][136]
    float* sAl = sAh + 64 * CPITCH;
    float* sWh = sAl + 64 * CPITCH;          // [64][72]
    float* sWl = sWh + 64 * WPITCH;
    int tid = threadIdx.x;
    int lane = tid & 31, wid = tid >> 5;
    int mb = (wid & 3) * 32, nb = (wid >> 2) * 32;
    int base = blockIdx.x * 128;

    stage_C_split(x, base, n, sAh, sAl, tid);
    stage_W_split<64>(W1a, sWh, sWl, tid);
    for (int i = blockIdx.x * NT + tid; i < n; i += gridDim.x * NT) g_cnt[i] = 0;
    __syncthreads();

    float Dt[2][4][4];
    mma_gemm<8, true>(sAh, sAl, sWh, sWl, mb, nb, lane, Dt);
    __syncthreads();

    relu_split(Dt, sAh, sAl, mb, nb, lane);
    stage_W_split<64>(W1b, sWh, sWl, tid);
    __syncthreads();

    mma_gemm<8, true>(sAh, sAl, sWh, sWl, mb, nb, lane, Dt);
    store_frag(Dt, g_y, base, n, mb, nb, lane);
}

// ---------------------------------------------------------------------------
// Bucket fill: one thread per edge. edge_index is INT32 (jax downcasts int64).
// ---------------------------------------------------------------------------
__global__ void fill_kernel(const int* __restrict__ ei, int E, int n) {
    int e = blockIdx.x * blockDim.x + threadIdx.x;
    if (e >= E) return;
    int row = ei[e];
    int col = ei[E + e];
    if ((unsigned)row >= (unsigned)n || (unsigned)col >= (unsigned)n) return;
    int idx = atomicAdd(&g_cnt[col], 1);
    if (idx < MAXDEG) g_tab[(size_t)col * MAXDEG + idx] = row;
}

// ---------------------------------------------------------------------------
// Gather + LN1: one node per WARP, 4-way partial sums (MLP=4 on L2 gathers).
// a = LN1(sum(y[src]) / cnt) -> g_a. (Unchanged from R13 — known good.)
// ---------------------------------------------------------------------------
__global__ __launch_bounds__(NT) void agg_kernel(
    const float* __restrict__ g1, const float* __restrict__ b1, int n)
{
    int t = blockIdx.x * NT + threadIdx.x;
    int node = t >> 5;
    int lane = t & 31;
    if (node >= n) return;

    int tc = g_cnt[node];
    int cnt = tc < MAXDEG ? tc : MAXDEG;
    const int* tp = g_tab + (size_t)node * MAXDEG;
    const char* yb = reinterpret_cast<const char*>(g_y) + lane * 8;

    u64 s0 = 0ULL, s1 = 0ULL, s2 = 0ULL, s3 = 0ULL;
    int e = 0;
    for (; e + 4 <= cnt; e += 4) {
        int i0 = tp[e], i1 = tp[e + 1], i2 = tp[e + 2], i3 = tp[e + 3];
        s0 = add2(s0, *reinterpret_cast<const u64*>(yb + (size_t)i0 * 256));
        s1 = add2(s1, *reinterpret_cast<const u64*>(yb + (size_t)i1 * 256));
        s2 = add2(s2, *reinterpret_cast<const u64*>(yb + (size_t)i2 * 256));
        s3 = add2(s3, *reinterpret_cast<const u64*>(yb + (size_t)i3 * 256));
    }
    for (; e < cnt; e++)
        s0 = add2(s0, *reinterpret_cast<const u64*>(yb + (size_t)tp[e] * 256));
    u64 s = add2(add2(s0, s1), add2(s2, s3));

    float inv = 1.0f / (float)(tc > 1 ? tc : 1);
    s = mul2(s, dup2(inv));

    float p = hsum2(s);
#pragma unroll
    for (int o = 16; o; o >>= 1) p += __shfl_xor_sync(0xffffffffu, p, o);
    float m = p * (1.f / 64.f);
    u64 d = add2(s, dup2(-m));
    float vp = hsum2(mul2(d, d));
#pragma unroll
    for (int o = 16; o; o >>= 1) vp += __shfl_xor_sync(0xffffffffu, vp, o);
    float r = rsqrtf(vp * (1.f / 64.f) + 1e-5f);
    u64 a = fma2(mul2(d, dup2(r)),
                 reinterpret_cast<const u64*>(g1)[lane],
                 reinterpret_cast<const u64*>(b1)[lane]);
    *reinterpret_cast<u64*>(g_a + (size_t)node * D + lane * 2) = a;
}

// ---------------------------------------------------------------------------
// Fused epilogue (tensor-core):
//  stage a split -> sA; GEMM1-A: D = a @ W2a[:,64:128]^T
//  fx = LN2(x + (x-a)*w)  (2 thr/node; a = hi+lo from sA) -> sA (split)
//  GEMM1-B: D += fx @ W2a[:,0:64]^T ; relu-split -> sA (hidden)
//  GEMM2:   out = H @ W2b^T
// smem: 26624 + 512 floats = 108544 B -> 2 CTAs/SM.
// ---------------------------------------------------------------------------
__global__ __launch_bounds__(NT, 2) void epilogue_kernel(
    const float* __restrict__ x,
    const float* __restrict__ wrep,
    const float* __restrict__ g2, const float* __restrict__ b2,
    const float* __restrict__ W2a, const float* __restrict__ W2b,
    float* __restrict__ out, int n)
{
    extern __shared__ __align__(16) float smem[];
    float* sAh = smem;
    float* sAl = sAh + 64 * CPITCH;
    float* sWh = sAl + 64 * CPITCH;
    float* sWl = sWh + 64 * WPITCH;
    float* sRed = sWl + 64 * WPITCH;         // [2][256]
    int tid = threadIdx.x;
    int lane = tid & 31, wid = tid >> 5;
    int mb = (wid & 3) * 32, nb = (wid >> 2) * 32;
    int base = blockIdx.x * 128;
    int col = tid & 127;
    int h = tid >> 7;
    int nid = base + col;
    bool valid = nid < n;
    int safe = valid ? nid : 0;

    stage_C_split(g_a, base, n, sAh, sAl, tid);       // A = a
    stage_W_split<128>(W2a + 64, sWh, sWl, tid);      // W2a RIGHT half
    __syncthreads();

    float Dt[2][4][4];
    mma_gemm<8, true>(sAh, sAl, sWh, sWl, mb, nb, lane, Dt);   // a-part
    __syncthreads();

    stage_W_split<128>(W2a, sWh, sWl, tid);           // W2a LEFT half

    // ---- fx = LN2(x + (x - a)*w); 2 threads/node, features [h*32,+32) ----
    {
        const u64* pw  = reinterpret_cast<const u64*>(wrep) + h * 16;
        const u64* pg2 = reinterpret_cast<const u64*>(g2) + h * 16;
        const u64* pb2 = reinterpret_cast<const u64*>(b2) + h * 16;
        u64 f2[16];
        const ulonglong2* xp = reinterpret_cast<const ulonglong2*>(x + (size_t)safe * D + h * 32);
#pragma unroll
        for (int q = 0; q < 8; q++) {
            ulonglong2 v = xp[q];
            u64 vx = valid ? v.x : 0ULL, vy = valid ? v.y : 0ULL;
            int r0 = (h * 32 + 4 * q) * CPITCH + col;
            int r1 = (h * 32 + 4 * q + 1) * CPITCH + col;
            int r2i = (h * 32 + 4 * q + 2) * CPITCH + col;
            int r3 = (h * 32 + 4 * q + 3) * CPITCH + col;
            u64 a0 = pack2(sAh[r0] + sAl[r0], sAh[r1] + sAl[r1]);
            u64 a1 = pack2(sAh[r2i] + sAl[r2i], sAh[r3] + sAl[r3]);
            u64 d0 = add2(vx, neg2(a0));
            u64 d1 = add2(vy, neg2(a1));
            f2[2 * q]     = fma2(d0, pw[2 * q], vx);
            f2[2 * q + 1] = fma2(d1, pw[2 * q + 1], vy);
        }
        u64 s = 0ULL;
#pragma unroll
        for (int i = 0; i < 16; i++) s = add2(s, f2[i]);
        sRed[tid] = hsum2(s);
        __syncthreads();
        float m2 = (sRed[tid] + sRed[tid ^ 128]) * (1.f / 64.f);
        u64 mneg = dup2(-m2);
        u64 vs = 0ULL;
#pragma unroll
        for (int i = 0; i < 16; i++) { u64 d = add2(f2[i], mneg); vs = fma2(d, d, vs); }
        sRed[256 + tid] = hsum2(vs);
        __syncthreads();
        float r2 = rsqrtf((sRed[256 + tid] + sRed[256 + (tid ^ 128)]) * (1.f / 64.f) + 1e-5f);
        u64 r22 = dup2(r2);
#pragma unroll
        for (int i = 0; i < 16; i++) {
            u64 fv = fma2(mul2(add2(f2[i], mneg), r22), pg2[i], pb2[i]);
            float lo, hi; unpack2(fv, lo, hi);
            float thi, tlo;
            split_tf32(lo, thi, tlo);
            sAh[(h * 32 + 2 * i) * CPITCH + col] = thi;
            sAl[(h * 32 + 2 * i) * CPITCH + col] = tlo;
            split_tf32(hi, thi, tlo);
            sAh[(h * 32 + 2 * i + 1) * CPITCH + col] = thi;
            sAl[(h * 32 + 2 * i + 1) * CPITCH + col] = tlo;
        }
    }
    __syncthreads();   // sA(fx) + sW(W2a left) ready

    mma_gemm<8, false>(sAh, sAl, sWh, sWl, mb, nb, lane, Dt);  // += fx-part
    __syncthreads();

    relu_split(Dt, sAh, sAl, mb, nb, lane);           // hidden (split)
    stage_W_split<64>(W2b, sWh, sWl, tid);
    __syncthreads();

    mma_gemm<8, true>(sAh, sAl, sWh, sWl, mb, nb, lane, Dt);
    store_frag(Dt, out, base, n, mb, nb, lane);
}

// ---------------------------------------------------------------------------
// Launch
// ---------------------------------------------------------------------------
extern "C" void kernel_launch(void* const* d_in, const int* in_sizes, int n_in,
                              void* d_out, int out_size) {
    const float* x   = (const float*)d_in[0];
    const int*   ei  = (const int*)d_in[1];      // int32 (jax downcasts int64)
    const float* W1a = (const float*)d_in[2];
    const float* W1b = (const float*)d_in[3];
    const float* g1  = (const float*)d_in[4];
    const float* b1  = (const float*)d_in[5];
    const float* w   = (const float*)d_in[6];
    const float* g2  = (const float*)d_in[7];
    const float* b2  = (const float*)d_in[8];
    const float* W2a = (const float*)d_in[9];
    const float* W2b = (const float*)d_in[10];
    float* out = (float*)d_out;

    int n = in_sizes[0] / D;
    int E = in_sizes[1] / 2;
    int blocks = (n + 127) / 128;

    const int MLP1_SMEM = (2 * 64 * CPITCH + 2 * 64 * WPITCH) * 4;         // 106496 B
    const int EPI_SMEM  = (2 * 64 * CPITCH + 2 * 64 * WPITCH + 512) * 4;   // 108544 B
    cudaFuncSetAttribute(mlp1_kernel, cudaFuncAttributeMaxDynamicSharedMemorySize, MLP1_SMEM);
    cudaFuncSetAttribute(epilogue_kernel, cudaFuncAttributeMaxDynamicSharedMemorySize, EPI_SMEM);

    mlp1_kernel<<<blocks, NT, MLP1_SMEM>>>(x, W1a, W1b, n);
    fill_kernel<<<(E + 255) / 256, 256>>>(ei, E, n);
    agg_kernel<<<(n * 32 + NT - 1) / NT, NT>>>(g1, b1, n);
    epilogue_kernel<<<blocks, NT, EPI_SMEM>>>(x, w, g2, b2, W2a, W2b, out, n);
}

// round 15
// speedup vs baseline: 1.3667x; 1.1070x over previous
#include <cuda_runtime.h>

#define D 64
#define NMAX 50000
#define EMAX 800000
#define MAXDEG 64

typedef unsigned long long u64;
typedef unsigned int u32;

// Scratch (device globals — no allocation allowed). 16B-aligned.
__device__ __align__(16) float g_y[NMAX * D];     // per-node MLP1 output
__device__ __align__(16) float g_c[NMAX * 2 * D]; // concat [fx | a] per node
__device__ int g_tab[NMAX * MAXDEG];              // bucket table: src rows per dst
__device__ int g_cnt[NMAX];                       // per-dst edge count (cursor)

// ---------------------------------------------------------------------------
// Packed fp32x2 helpers (agg kernel LN math)
// ---------------------------------------------------------------------------
__device__ __forceinline__ u64 pack2(float lo, float hi) {
    u64 r; asm("mov.b64 %0, {%1, %2};" : "=l"(r) : "f"(lo), "f"(hi)); return r;
}
__device__ __forceinline__ u64 dup2(float s) { return pack2(s, s); }
__device__ __forceinline__ void unpack2(u64 v, float& lo, float& hi) {
    asm("mov.b64 {%0, %1}, %2;" : "=f"(lo), "=f"(hi) : "l"(v));
}
__device__ __forceinline__ u64 fma2(u64 a, u64 b, u64 c) {
    u64 d; asm("fma.rn.f32x2 %0, %1, %2, %3;" : "=l"(d) : "l"(a), "l"(b), "l"(c)); return d;
}
__device__ __forceinline__ u64 add2(u64 a, u64 b) {
    u64 d; asm("add.rn.f32x2 %0, %1, %2;" : "=l"(d) : "l"(a), "l"(b)); return d;
}
__device__ __forceinline__ u64 mul2(u64 a, u64 b) {
    u64 d; asm("mul.rn.f32x2 %0, %1, %2;" : "=l"(d) : "l"(a), "l"(b)); return d;
}
__device__ __forceinline__ u64 neg2(u64 a) { return a ^ 0x8000000080000000ULL; }
__device__ __forceinline__ float hsum2(u64 v) { float lo, hi; unpack2(v, lo, hi); return lo + hi; }

// bf16 2-term split of a float pair: hp = {bf16(f1)|bf16(f0)}, lp = residuals.
__device__ __forceinline__ void split_bf16x2(float f0, float f1, u32& hp, u32& lp) {
    asm("cvt.rn.bf16x2.f32 %0, %1, %2;" : "=r"(hp) : "f"(f1), "f"(f0));
    float h0 = __uint_as_float(hp << 16);
    float h1 = __uint_as_float(hp & 0xffff0000u);
    asm("cvt.rn.bf16x2.f32 %0, %1, %2;" : "=r"(lp) : "f"(f1 - h1), "f"(f0 - h0));
}

#define CPITCH 136   // u32 pitch, ==8 mod 32 -> frag banks 8*lc+lr: permutation
#define WPITCH 72
#define NT 256

// m16n8k16 bf16 mma, fp32 accumulate in place.
__device__ __forceinline__ void mma16(float d[4], const u32 a[4], const u32 b[2]) {
    asm("mma.sync.aligned.m16n8k16.row.col.f32.bf16.bf16.f32 "
        "{%0,%1,%2,%3}, {%4,%5,%6,%7}, {%8,%9}, {%0,%1,%2,%3};"
        : "+f"(d[0]), "+f"(d[1]), "+f"(d[2]), "+f"(d[3])
        : "r"(a[0]), "r"(a[1]), "r"(a[2]), "r"(a[3]), "r"(b[0]), "r"(b[1]));
}

// ---------------------------------------------------------------------------
// 3xBF16 GEMM: block tile 128m x 64n, K = KC*16. 8 warps: mb=(wid&3)*32,
// nb=(wid>>2)*32; warp tile 32x32 = 2 m-tiles x 4 n-tiles.
// sA: u32[k/2][m] (bf16 pair along k), sW: u32[k/2][n]. D accs fp32.
// ---------------------------------------------------------------------------
template <int KC, bool INIT>
__device__ __forceinline__ void mma_gemm(
    const u32* __restrict__ sAh, const u32* __restrict__ sAl,
    const u32* __restrict__ sWh, const u32* __restrict__ sWl,
    int mb, int nb, int lane, float Dt[2][4][4])
{
    if (INIT) {
#pragma unroll
        for (int t = 0; t < 2; t++)
#pragma unroll
            for (int u = 0; u < 4; u++)
#pragma unroll
                for (int e = 0; e < 4; e++) Dt[t][u][e] = 0.f;
    }
    int lr = lane >> 2, lc = lane & 3;
#pragma unroll
    for (int kc = 0; kc < KC; kc++) {
        int r0 = kc * 8 + lc, r1 = kc * 8 + lc + 4;
        u32 Ah[2][4], Al[2][4], Bh[4][2], Bl[4][2];
#pragma unroll
        for (int t = 0; t < 2; t++) {
            int m = mb + t * 16 + lr;
            Ah[t][0] = sAh[r0 * CPITCH + m];
            Ah[t][1] = sAh[r0 * CPITCH + m + 8];
            Ah[t][2] = sAh[r1 * CPITCH + m];
            Ah[t][3] = sAh[r1 * CPITCH + m + 8];
            Al[t][0] = sAl[r0 * CPITCH + m];
            Al[t][1] = sAl[r0 * CPITCH + m + 8];
            Al[t][2] = sAl[r1 * CPITCH + m];
            Al[t][3] = sAl[r1 * CPITCH + m + 8];
        }
#pragma unroll
        for (int u = 0; u < 4; u++) {
            int nn = nb + u * 8 + lr;
            Bh[u][0] = sWh[r0 * WPITCH + nn];
            Bh[u][1] = sWh[r1 * WPITCH + nn];
            Bl[u][0] = sWl[r0 * WPITCH + nn];
            Bl[u][1] = sWl[r1 * WPITCH + nn];
        }
#pragma unroll
        for (int t = 0; t < 2; t++)
#pragma unroll
            for (int u = 0; u < 4; u++) {
                mma16(Dt[t][u], Ah[t], Bh[u]);
                mma16(Dt[t][u], Ah[t], Bl[u]);
                mma16(Dt[t][u], Al[t], Bh[u]);
            }
    }
}

// Stage activations [node][KF] fp32 row-major -> split u32 [k2][node].
template <int KF>
__device__ __forceinline__ void stage_C_split(const float* __restrict__ g, int base, int n,
                                              u32* __restrict__ sAh, u32* __restrict__ sAl,
                                              int tid) {
    const int KF4 = KF / 4;
    for (int idx = tid; idx < 128 * KF4; idx += NT) {
        int k4 = idx >> 7, node = idx & 127;
        float4 v = make_float4(0.f, 0.f, 0.f, 0.f);
        if (base + node < n) v = reinterpret_cast<const float4*>(g + (size_t)(base + node) * KF)[k4];
        u32 hp0, lp0, hp1, lp1;
        split_bf16x2(v.x, v.y, hp0, lp0);
        split_bf16x2(v.z, v.w, hp1, lp1);
        sAh[(2 * k4) * CPITCH + node] = hp0;
        sAh[(2 * k4 + 1) * CPITCH + node] = hp1;
        sAl[(2 * k4) * CPITCH + node] = lp0;
        sAl[(2 * k4 + 1) * CPITCH + node] = lp1;
    }
}

// Stage weights w[j][k] (64 rows, KF cols, row stride RSTRIDE) -> split u32 [k2][j].
template <int KF, int RSTRIDE>
__device__ __forceinline__ void stage_W_split(const float* __restrict__ w,
                                              u32* __restrict__ sWh, u32* __restrict__ sWl,
                                              int tid) {
    const int KF4 = KF / 4;
    for (int idx = tid; idx < 64 * KF4; idx += NT) {
        int k4 = idx / 64, j = idx & 63;
        float4 v = *reinterpret_cast<const float4*>(w + j * RSTRIDE + 4 * k4);
        u32 hp0, lp0, hp1, lp1;
        split_bf16x2(v.x, v.y, hp0, lp0);
        split_bf16x2(v.z, v.w, hp1, lp1);
        sWh[(2 * k4) * WPITCH + j] = hp0;
        sWh[(2 * k4 + 1) * WPITCH + j] = hp1;
        sWl[(2 * k4) * WPITCH + j] = lp0;
        sWl[(2 * k4 + 1) * WPITCH + j] = lp1;
    }
}

// ReLU accs -> split hidden tile as next GEMM's A: u32 [j/2][m].
// n0 = nb + u*8 + 2*lc is even, so (n0, n0+1) is exactly one bf16x2 k-pair.
__device__ __forceinline__ void relu_split(float Dt[2][4][4],
                                           u32* __restrict__ sAh, u32* __restrict__ sAl,
                                           int mb, int nb, int lane) {
    int lr = lane >> 2, lc = lane & 3;
#pragma unroll
    for (int t = 0; t < 2; t++)
#pragma unroll
        for (int u = 0; u < 4; u++) {
            int m0 = mb + t * 16 + lr;
            int k2 = nb / 2 + u * 4 + lc;
            u32 hp, lp;
            split_bf16x2(fmaxf(Dt[t][u][0], 0.f), fmaxf(Dt[t][u][1], 0.f), hp, lp);
            sAh[k2 * CPITCH + m0] = hp;
            sAl[k2 * CPITCH + m0] = lp;
            split_bf16x2(fmaxf(Dt[t][u][2], 0.f), fmaxf(Dt[t][u][3], 0.f), hp, lp);
            sAh[k2 * CPITCH + m0 + 8] = hp;
            sAl[k2 * CPITCH + m0 + 8] = lp;
        }
}

// Store accs to out[node][n], guarded; paired 8B stores.
__device__ __forceinline__ void store_frag(float Dt[2][4][4], float* __restrict__ out,
                                           int base, int n, int mb, int nb, int lane) {
    int lr = lane >> 2, lc = lane & 3;
#pragma unroll
    for (int t = 0; t < 2; t++) {
        int m0 = mb + t * 16 + lr;
#pragma unroll
        for (int u = 0; u < 4; u++) {
            int n0 = nb + u * 8 + 2 * lc;
            int node0 = base + m0;
            int node1 = base + m0 + 8;
            if (node0 < n)
                *reinterpret_cast<u64*>(out + (size_t)node0 * D + n0) = pack2(Dt[t][u][0], Dt[t][u][1]);
            if (node1 < n)
                *reinterpret_cast<u64*>(out + (size_t)node1 * D + n0) = pack2(Dt[t][u][2], Dt[t][u][3]);
        }
    }
}

// ---------------------------------------------------------------------------
// MLP1: y = relu(x @ W1a^T) @ W1b^T  (per-node; 16x FLOP cut vs per-edge).
// 3xBF16 tensor-core GEMMs. Also zeroes g_cnt.
// smem: (2*32*136 + 2*32*72)*4 = 53248 B.
// ---------------------------------------------------------------------------
__global__ __launch_bounds__(NT, 2) void mlp1_kernel(
    const float* __restrict__ x, const float* __restrict__ W1a,
    const float* __restrict__ W1b, int n)
{
    extern __shared__ __align__(16) u32 smem[];
    u32* sAh = smem;                     // [32][136]
    u32* sAl = sAh + 32 * CPITCH;
    u32* sWh = sAl + 32 * CPITCH;        // [32][72]
    u32* sWl = sWh + 32 * WPITCH;
    int tid = threadIdx.x;
    int lane = tid & 31, wid = tid >> 5;
    int mb = (wid & 3) * 32, nb = (wid >> 2) * 32;
    int base = blockIdx.x * 128;

    stage_C_split<64>(x, base, n, sAh, sAl, tid);
    stage_W_split<64, 64>(W1a, sWh, sWl, tid);
    for (int i = blockIdx.x * NT + tid; i < n; i += gridDim.x * NT) g_cnt[i] = 0;
    __syncthreads();

    float Dt[2][4][4];
    mma_gemm<4, true>(sAh, sAl, sWh, sWl, mb, nb, lane, Dt);
    __syncthreads();

    relu_split(Dt, sAh, sAl, mb, nb, lane);
    stage_W_split<64, 64>(W1b, sWh, sWl, tid);
    __syncthreads();

    mma_gemm<4, true>(sAh, sAl, sWh, sWl, mb, nb, lane, Dt);
    store_frag(Dt, g_y, base, n, mb, nb, lane);
}

// ---------------------------------------------------------------------------
// Bucket fill: one thread per edge. edge_index is INT32 (jax downcasts int64).
// ---------------------------------------------------------------------------
__global__ void fill_kernel(const int* __restrict__ ei, int E, int n) {
    int e = blockIdx.x * blockDim.x + threadIdx.x;
    if (e >= E) return;
    int row = ei[e];
    int col = ei[E + e];
    if ((unsigned)row >= (unsigned)n || (unsigned)col >= (unsigned)n) return;
    int idx = atomicAdd(&g_cnt[col], 1);
    if (idx < MAXDEG) g_tab[(size_t)col * MAXDEG + idx] = row;
}

// ---------------------------------------------------------------------------
// Gather + LN1 + LN2 fused: one node per WARP, 4-way partial sums (MLP=4).
//  a  = LN1(sum(y[src]) / cnt)
//  fx = LN2(x + (x - a)*w)
//  g_c[node] = [fx(0..63) | a(64..127)]  — full concat row for the epilogue.
// ---------------------------------------------------------------------------
__global__ __launch_bounds__(NT) void agg_kernel(
    const float* __restrict__ x,
    const float* __restrict__ g1, const float* __restrict__ b1,
    const float* __restrict__ wrep,
    const float* __restrict__ g2, const float* __restrict__ b2, int n)
{
    int t = blockIdx.x * NT + threadIdx.x;
    int node = t >> 5;
    int lane = t & 31;
    if (node >= n) return;

    int tc = g_cnt[node];
    int cnt = tc < MAXDEG ? tc : MAXDEG;
    const int* tp = g_tab + (size_t)node * MAXDEG;
    const char* yb = reinterpret_cast<const char*>(g_y) + lane * 8;

    u64 s0 = 0ULL, s1 = 0ULL, s2 = 0ULL, s3 = 0ULL;
    int e = 0;
    for (; e + 4 <= cnt; e += 4) {
        int i0 = tp[e], i1 = tp[e + 1], i2 = tp[e + 2], i3 = tp[e + 3];
        s0 = add2(s0, *reinterpret_cast<const u64*>(yb + (size_t)i0 * 256));
        s1 = add2(s1, *reinterpret_cast<const u64*>(yb + (size_t)i1 * 256));
        s2 = add2(s2, *reinterpret_cast<const u64*>(yb + (size_t)i2 * 256));
        s3 = add2(s3, *reinterpret_cast<const u64*>(yb + (size_t)i3 * 256));
    }
    for (; e < cnt; e++)
        s0 = add2(s0, *reinterpret_cast<const u64*>(yb + (size_t)tp[e] * 256));
    u64 s = add2(add2(s0, s1), add2(s2, s3));

    float inv = 1.0f / (float)(tc > 1 ? tc : 1);
    s = mul2(s, dup2(inv));

    // LN1 (warp shuffles)
    float p = hsum2(s);
#pragma unroll
    for (int o = 16; o; o >>= 1) p += __shfl_xor_sync(0xffffffffu, p, o);
    float m = p * (1.f / 64.f);
    u64 d = add2(s, dup2(-m));
    float vp = hsum2(mul2(d, d));
#pragma unroll
    for (int o = 16; o; o >>= 1) vp += __shfl_xor_sync(0xffffffffu, vp, o);
    float r = rsqrtf(vp * (1.f / 64.f) + 1e-5f);
    u64 a = fma2(mul2(d, dup2(r)),
                 reinterpret_cast<const u64*>(g1)[lane],
                 reinterpret_cast<const u64*>(b1)[lane]);

    // fx = LN2(x + (x - a)*w)
    u64 xv = *reinterpret_cast<const u64*>(x + (size_t)node * D + lane * 2);
    u64 f = fma2(add2(xv, neg2(a)), reinterpret_cast<const u64*>(wrep)[lane], xv);
    p = hsum2(f);
#pragma unroll
    for (int o = 16; o; o >>= 1) p += __shfl_xor_sync(0xffffffffu, p, o);
    m = p * (1.f / 64.f);
    d = add2(f, dup2(-m));
    vp = hsum2(mul2(d, d));
#pragma unroll
    for (int o = 16; o; o >>= 1) vp += __shfl_xor_sync(0xffffffffu, vp, o);
    r = rsqrtf(vp * (1.f / 64.f) + 1e-5f);
    u64 fx = fma2(mul2(d, dup2(r)),
                  reinterpret_cast<const u64*>(g2)[lane],
                  reinterpret_cast<const u64*>(b2)[lane]);

    u64* cp = reinterpret_cast<u64*>(g_c + (size_t)node * 2 * D);
    cp[lane] = fx;
    cp[32 + lane] = a;
}

// ---------------------------------------------------------------------------
// Epilogue (pure batched MLP now):
//  stage g_c split (K=128) + stage W2a (K=128) -> GEMM1 -> relu-split ->
//  stage W2b (K=64) -> GEMM2 -> out.  Only 3 syncs.
// smem: (2*64*136 + 2*64*72)*4 = 106496 B -> 2 CTAs/SM.
// ---------------------------------------------------------------------------
__global__ __launch_bounds__(NT, 2) void epilogue_kernel(
    const float* __restrict__ W2a, const float* __restrict__ W2b,
    float* __restrict__ out, int n)
{
    extern __shared__ __align__(16) u32 smem[];
    u32* sAh = smem;                     // [64][136]
    u32* sAl = sAh + 64 * CPITCH;
    u32* sWh = sAl + 64 * CPITCH;        // [64][72]
    u32* sWl = sWh + 64 * WPITCH;
    int tid = threadIdx.x;
    int lane = tid & 31, wid = tid >> 5;
    int mb = (wid & 3) * 32, nb = (wid >> 2) * 32;
    int base = blockIdx.x * 128;

    stage_C_split<128>(g_c, base, n, sAh, sAl, tid);
    stage_W_split<128, 128>(W2a, sWh, sWl, tid);
    __syncthreads();

    float Dt[2][4][4];
    mma_gemm<8, true>(sAh, sAl, sWh, sWl, mb, nb, lane, Dt);
    __syncthreads();

    relu_split(Dt, sAh, sAl, mb, nb, lane);       // hidden -> sA rows 0..31
    stage_W_split<64, 64>(W2b, sWh, sWl, tid);
    __syncthreads();

    mma_gemm<4, true>(sAh, sAl, sWh, sWl, mb, nb, lane, Dt);
    store_frag(Dt, out, base, n, mb, nb, lane);
}

// ---------------------------------------------------------------------------
// Launch
// ---------------------------------------------------------------------------
extern "C" void kernel_launch(void* const* d_in, const int* in_sizes, int n_in,
                              void* d_out, int out_size) {
    const float* x   = (const float*)d_in[0];
    const int*   ei  = (const int*)d_in[1];      // int32 (jax downcasts int64)
    const float* W1a = (const float*)d_in[2];
    const float* W1b = (const float*)d_in[3];
    const float* g1  = (const float*)d_in[4];
    const float* b1  = (const float*)d_in[5];
    const float* w   = (const float*)d_in[6];
    const float* g2  = (const float*)d_in[7];
    const float* b2  = (const float*)d_in[8];
    const float* W2a = (const float*)d_in[9];
    const float* W2b = (const float*)d_in[10];
    float* out = (float*)d_out;

    int n = in_sizes[0] / D;
    int E = in_sizes[1] / 2;
    int blocks = (n + 127) / 128;

    const int MLP1_SMEM = (2 * 32 * CPITCH + 2 * 32 * WPITCH) * 4;   // 53248 B
    const int EPI_SMEM  = (2 * 64 * CPITCH + 2 * 64 * WPITCH) * 4;   // 106496 B
    cudaFuncSetAttribute(mlp1_kernel, cudaFuncAttributeMaxDynamicSharedMemorySize, MLP1_SMEM);
    cudaFuncSetAttribute(epilogue_kernel, cudaFuncAttributeMaxDynamicSharedMemorySize, EPI_SMEM);

    mlp1_kernel<<<blocks, NT, MLP1_SMEM>>>(x, W1a, W1b, n);
    fill_kernel<<<(E + 255) / 256, 256>>>(ei, E, n);
    agg_kernel<<<(n * 32 + NT - 1) / NT, NT>>>(x, g1, b1, w, g2, b2, n);
    epilogue_kernel<<<blocks, NT, EPI_SMEM>>>(W2a, W2b, out, n);
}

// round 16
// speedup vs baseline: 1.5505x; 1.1345x over previous
#include <cuda_runtime.h>

#define D 64
#define NMAX 50000
#define EMAX 800000
#define MAXDEG 64

typedef unsigned long long u64;
typedef unsigned int u32;

// Scratch (device globals — no allocation allowed). 16B-aligned.
__device__ __align__(16) float g_y[NMAX * D];     // per-node MLP1 output (fp32)
__device__ __align__(16) u32 g_ch[NMAX * D];      // concat [fx|a], bf16x2 hi pairs
__device__ __align__(16) u32 g_cl[NMAX * D];      // concat residual lo pairs
__device__ int g_tab[NMAX * MAXDEG];              // bucket table: src rows per dst
__device__ int g_cnt[NMAX];                       // per-dst edge count (cursor)

#define CPITCH 136   // u32 pitch, ==8 mod 32 -> frag banks 8*lc+lr: permutation
#define WPITCH 72
#define NT 256

// Pre-split weights in final [k2][j] pitched layout (written by fill_kernel).
__device__ __align__(16) u32 g_w2a_h[64 * WPITCH];
__device__ __align__(16) u32 g_w2a_l[64 * WPITCH];
__device__ __align__(16) u32 g_w2b_h[32 * WPITCH];
__device__ __align__(16) u32 g_w2b_l[32 * WPITCH];

// ---------------------------------------------------------------------------
// Packed fp32x2 helpers (agg kernel LN math)
// ---------------------------------------------------------------------------
__device__ __forceinline__ u64 pack2(float lo, float hi) {
    u64 r; asm("mov.b64 %0, {%1, %2};" : "=l"(r) : "f"(lo), "f"(hi)); return r;
}
__device__ __forceinline__ u64 dup2(float s) { return pack2(s, s); }
__device__ __forceinline__ void unpack2(u64 v, float& lo, float& hi) {
    asm("mov.b64 {%0, %1}, %2;" : "=f"(lo), "=f"(hi) : "l"(v));
}
__device__ __forceinline__ u64 fma2(u64 a, u64 b, u64 c) {
    u64 d; asm("fma.rn.f32x2 %0, %1, %2, %3;" : "=l"(d) : "l"(a), "l"(b), "l"(c)); return d;
}
__device__ __forceinline__ u64 add2(u64 a, u64 b) {
    u64 d; asm("add.rn.f32x2 %0, %1, %2;" : "=l"(d) : "l"(a), "l"(b)); return d;
}
__device__ __forceinline__ u64 mul2(u64 a, u64 b) {
    u64 d; asm("mul.rn.f32x2 %0, %1, %2;" : "=l"(d) : "l"(a), "l"(b)); return d;
}
__device__ __forceinline__ u64 neg2(u64 a) { return a ^ 0x8000000080000000ULL; }
__device__ __forceinline__ float hsum2(u64 v) { float lo, hi; unpack2(v, lo, hi); return lo + hi; }

// bf16 2-term split of a float pair: hp = {bf16(f1)|bf16(f0)}, lp = residuals.
__device__ __forceinline__ void split_bf16x2(float f0, float f1, u32& hp, u32& lp) {
    asm("cvt.rn.bf16x2.f32 %0, %1, %2;" : "=r"(hp) : "f"(f1), "f"(f0));
    float h0 = __uint_as_float(hp << 16);
    float h1 = __uint_as_float(hp & 0xffff0000u);
    asm("cvt.rn.bf16x2.f32 %0, %1, %2;" : "=r"(lp) : "f"(f1 - h1), "f"(f0 - h0));
}

// m16n8k16 bf16 mma, fp32 accumulate in place.
__device__ __forceinline__ void mma16(float d[4], const u32 a[4], const u32 b[2]) {
    asm("mma.sync.aligned.m16n8k16.row.col.f32.bf16.bf16.f32 "
        "{%0,%1,%2,%3}, {%4,%5,%6,%7}, {%8,%9}, {%0,%1,%2,%3};"
        : "+f"(d[0]), "+f"(d[1]), "+f"(d[2]), "+f"(d[3])
        : "r"(a[0]), "r"(a[1]), "r"(a[2]), "r"(a[3]), "r"(b[0]), "r"(b[1]));
}

// ---------------------------------------------------------------------------
// 3xBF16 GEMM: block tile 128m x 64n, K = KC*16. 8 warps: mb=(wid&3)*32,
// nb=(wid>>2)*32; warp tile 32x32 = 2 m-tiles x 4 n-tiles.
// ---------------------------------------------------------------------------
template <int KC, bool INIT>
__device__ __forceinline__ void mma_gemm(
    const u32* __restrict__ sAh, const u32* __restrict__ sAl,
    const u32* __restrict__ sWh, const u32* __restrict__ sWl,
    int mb, int nb, int lane, float Dt[2][4][4])
{
    if (INIT) {
#pragma unroll
        for (int t = 0; t < 2; t++)
#pragma unroll
            for (int u = 0; u < 4; u++)
#pragma unroll
                for (int e = 0; e < 4; e++) Dt[t][u][e] = 0.f;
    }
    int lr = lane >> 2, lc = lane & 3;
#pragma unroll
    for (int kc = 0; kc < KC; kc++) {
        int r0 = kc * 8 + lc, r1 = kc * 8 + lc + 4;
        u32 Ah[2][4], Al[2][4], Bh[4][2], Bl[4][2];
#pragma unroll
        for (int t = 0; t < 2; t++) {
            int m = mb + t * 16 + lr;
            Ah[t][0] = sAh[r0 * CPITCH + m];
            Ah[t][1] = sAh[r0 * CPITCH + m + 8];
            Ah[t][2] = sAh[r1 * CPITCH + m];
            Ah[t][3] = sAh[r1 * CPITCH + m + 8];
            Al[t][0] = sAl[r0 * CPITCH + m];
            Al[t][1] = sAl[r0 * CPITCH + m + 8];
            Al[t][2] = sAl[r1 * CPITCH + m];
            Al[t][3] = sAl[r1 * CPITCH + m + 8];
        }
#pragma unroll
        for (int u = 0; u < 4; u++) {
            int nn = nb + u * 8 + lr;
            Bh[u][0] = sWh[r0 * WPITCH + nn];
            Bh[u][1] = sWh[r1 * WPITCH + nn];
            Bl[u][0] = sWl[r0 * WPITCH + nn];
            Bl[u][1] = sWl[r1 * WPITCH + nn];
        }
#pragma unroll
        for (int t = 0; t < 2; t++)
#pragma unroll
            for (int u = 0; u < 4; u++) {
                mma16(Dt[t][u], Ah[t], Bh[u]);
                mma16(Dt[t][u], Ah[t], Bl[u]);
                mma16(Dt[t][u], Al[t], Bh[u]);
            }
    }
}

// Stage fp32 activations [node][KF] -> split u32 [k2][node] (cvt path, mlp1).
template <int KF>
__device__ __forceinline__ void stage_C_split(const float* __restrict__ g, int base, int n,
                                              u32* __restrict__ sAh, u32* __restrict__ sAl,
                                              int tid) {
    const int KF4 = KF / 4;
    for (int idx = tid; idx < 128 * KF4; idx += NT) {
        int k4 = idx >> 7, node = idx & 127;
        float4 v = make_float4(0.f, 0.f, 0.f, 0.f);
        if (base + node < n) v = reinterpret_cast<const float4*>(g + (size_t)(base + node) * KF)[k4];
        u32 hp0, lp0, hp1, lp1;
        split_bf16x2(v.x, v.y, hp0, lp0);
        split_bf16x2(v.z, v.w, hp1, lp1);
        sAh[(2 * k4) * CPITCH + node] = hp0;
        sAh[(2 * k4 + 1) * CPITCH + node] = hp1;
        sAl[(2 * k4) * CPITCH + node] = lp0;
        sAl[(2 * k4 + 1) * CPITCH + node] = lp1;
    }
}

// Stage fp32 weights w[j][k] (64 rows, KF cols) -> split u32 [k2][j] (mlp1).
template <int KF, int RSTRIDE>
__device__ __forceinline__ void stage_W_split(const float* __restrict__ w,
                                              u32* __restrict__ sWh, u32* __restrict__ sWl,
                                              int tid) {
    const int KF4 = KF / 4;
    for (int idx = tid; idx < 64 * KF4; idx += NT) {
        int k4 = idx / 64, j = idx & 63;
        float4 v = *reinterpret_cast<const float4*>(w + j * RSTRIDE + 4 * k4);
        u32 hp0, lp0, hp1, lp1;
        split_bf16x2(v.x, v.y, hp0, lp0);
        split_bf16x2(v.z, v.w, hp1, lp1);
        sWh[(2 * k4) * WPITCH + j] = hp0;
        sWh[(2 * k4 + 1) * WPITCH + j] = hp1;
        sWl[(2 * k4) * WPITCH + j] = lp0;
        sWl[(2 * k4 + 1) * WPITCH + j] = lp1;
    }
}

// Copy pre-split C half h (k2 in [h*32, h*32+32)) from g_ch/g_cl -> sA.
__device__ __forceinline__ void stage_C_copy(int h, int base, int n,
                                             u32* __restrict__ sAh, u32* __restrict__ sAl,
                                             int tid) {
    for (int idx = tid; idx < 1024; idx += NT) {
        int node = idx & 127, q = idx >> 7;     // q in 0..7, 4 k2-rows each
        uint4 vh = make_uint4(0u, 0u, 0u, 0u), vl = vh;
        if (base + node < n) {
            size_t off = (size_t)(base + node) * 64 + h * 32 + 4 * q;
            vh = *reinterpret_cast<const uint4*>(g_ch + off);
            vl = *reinterpret_cast<const uint4*>(g_cl + off);
        }
        sAh[(4 * q + 0) * CPITCH + node] = vh.x;
        sAh[(4 * q + 1) * CPITCH + node] = vh.y;
        sAh[(4 * q + 2) * CPITCH + node] = vh.z;
        sAh[(4 * q + 3) * CPITCH + node] = vh.w;
        sAl[(4 * q + 0) * CPITCH + node] = vl.x;
        sAl[(4 * q + 1) * CPITCH + node] = vl.y;
        sAl[(4 * q + 2) * CPITCH + node] = vl.z;
        sAl[(4 * q + 3) * CPITCH + node] = vl.w;
    }
}

// Contiguous uint4 copy of nwords u32 (nwords % 4 == 0, 16B-aligned).
__device__ __forceinline__ void copy_block(const u32* __restrict__ src,
                                           u32* __restrict__ dst, int nwords, int tid) {
    for (int i = tid * 4; i < nwords; i += NT * 4)
        *reinterpret_cast<uint4*>(dst + i) = *reinterpret_cast<const uint4*>(src + i);
}

// ReLU accs -> split hidden tile as next GEMM's A: u32 [j/2][m].
__device__ __forceinline__ void relu_split(float Dt[2][4][4],
                                           u32* __restrict__ sAh, u32* __restrict__ sAl,
                                           int mb, int nb, int lane) {
    int lr = lane >> 2, lc = lane & 3;
#pragma unroll
    for (int t = 0; t < 2; t++)
#pragma unroll
        for (int u = 0; u < 4; u++) {
            int m0 = mb + t * 16 + lr;
            int k2 = nb / 2 + u * 4 + lc;
            u32 hp, lp;
            split_bf16x2(fmaxf(Dt[t][u][0], 0.f), fmaxf(Dt[t][u][1], 0.f), hp, lp);
            sAh[k2 * CPITCH + m0] = hp;
            sAl[k2 * CPITCH + m0] = lp;
            split_bf16x2(fmaxf(Dt[t][u][2], 0.f), fmaxf(Dt[t][u][3], 0.f), hp, lp);
            sAh[k2 * CPITCH + m0 + 8] = hp;
            sAl[k2 * CPITCH + m0 + 8] = lp;
        }
}

// Store accs to out[node][n], guarded; paired 8B stores.
__device__ __forceinline__ void store_frag(float Dt[2][4][4], float* __restrict__ out,
                                           int base, int n, int mb, int nb, int lane) {
    int lr = lane >> 2, lc = lane & 3;
#pragma unroll
    for (int t = 0; t < 2; t++) {
        int m0 = mb + t * 16 + lr;
#pragma unroll
        for (int u = 0; u < 4; u++) {
            int n0 = nb + u * 8 + 2 * lc;
            int node0 = base + m0;
            int node1 = base + m0 + 8;
            if (node0 < n)
                *reinterpret_cast<u64*>(out + (size_t)node0 * D + n0) = pack2(Dt[t][u][0], Dt[t][u][1]);
            if (node1 < n)
                *reinterpret_cast<u64*>(out + (size_t)node1 * D + n0) = pack2(Dt[t][u][2], Dt[t][u][3]);
        }
    }
}

// ---------------------------------------------------------------------------
// MLP1: y = relu(x @ W1a^T) @ W1b^T  (per-node; 16x FLOP cut vs per-edge).
// 3xBF16 tensor-core GEMMs. Also zeroes g_cnt.
// smem 53248 B, 3 CTAs/SM -> 391 blocks fit in ONE wave (444 slots).
// ---------------------------------------------------------------------------
__global__ __launch_bounds__(NT, 3) void mlp1_kernel(
    const float* __restrict__ x, const float* __restrict__ W1a,
    const float* __restrict__ W1b, int n)
{
    extern __shared__ __align__(16) u32 smem[];
    u32* sAh = smem;                     // [32][136]
    u32* sAl = sAh + 32 * CPITCH;
    u32* sWh = sAl + 32 * CPITCH;        // [32][72]
    u32* sWl = sWh + 32 * WPITCH;
    int tid = threadIdx.x;
    int lane = tid & 31, wid = tid >> 5;
    int mb = (wid & 3) * 32, nb = (wid >> 2) * 32;
    int base = blockIdx.x * 128;

    stage_C_split<64>(x, base, n, sAh, sAl, tid);
    stage_W_split<64, 64>(W1a, sWh, sWl, tid);
    for (int i = blockIdx.x * NT + tid; i < n; i += gridDim.x * NT) g_cnt[i] = 0;
    __syncthreads();

    float Dt[2][4][4];
    mma_gemm<4, true>(sAh, sAl, sWh, sWl, mb, nb, lane, Dt);
    __syncthreads();

    relu_split(Dt, sAh, sAl, mb, nb, lane);
    stage_W_split<64, 64>(W1b, sWh, sWl, tid);
    __syncthreads();

    mma_gemm<4, true>(sAh, sAl, sWh, sWl, mb, nb, lane, Dt);
    store_frag(Dt, g_y, base, n, mb, nb, lane);
}

// ---------------------------------------------------------------------------
// Bucket fill + epilogue weight pre-split. First WBLK blocks split W2a/W2b
// into the final pitched layout; the rest bucket the edges.
// edge_index is INT32 (jax downcasts int64).
// ---------------------------------------------------------------------------
#define WBLK 12
__global__ void fill_kernel(const int* __restrict__ ei, int E, int n,
                            const float* __restrict__ W2a, const float* __restrict__ W2b) {
    if (blockIdx.x < WBLK) {
        int item = blockIdx.x * 256 + threadIdx.x;   // 0..3071
        const float* w; u32 *dh, *dl; int k4, j, rs;
        if (item < 2048) { w = W2a; dh = g_w2a_h; dl = g_w2a_l; k4 = item >> 6; j = item & 63; rs = 128; }
        else { item -= 2048; w = W2b; dh = g_w2b_h; dl = g_w2b_l; k4 = item >> 6; j = item & 63; rs = 64; }
        float4 v = *reinterpret_cast<const float4*>(w + j * rs + 4 * k4);
        u32 hp0, lp0, hp1, lp1;
        split_bf16x2(v.x, v.y, hp0, lp0);
        split_bf16x2(v.z, v.w, hp1, lp1);
        dh[(2 * k4) * WPITCH + j] = hp0; dh[(2 * k4 + 1) * WPITCH + j] = hp1;
        dl[(2 * k4) * WPITCH + j] = lp0; dl[(2 * k4 + 1) * WPITCH + j] = lp1;
        return;
    }
    int e = (blockIdx.x - WBLK) * 256 + threadIdx.x;
    if (e >= E) return;
    int row = ei[e];
    int col = ei[E + e];
    if ((unsigned)row >= (unsigned)n || (unsigned)col >= (unsigned)n) return;
    int idx = atomicAdd(&g_cnt[col], 1);
    if (idx < MAXDEG) g_tab[(size_t)col * MAXDEG + idx] = row;
}

// ---------------------------------------------------------------------------
// Gather + LN1 + LN2 fused: one node per WARP, 4-way partial sums (MLP=4).
//  a = LN1(sum(y[src])/cnt); fx = LN2(x + (x-a)*w)
//  Writes pre-split concat row: g_ch/g_cl[node][0..31]=fx, [32..63]=a.
// ---------------------------------------------------------------------------
__global__ __launch_bounds__(NT) void agg_kernel(
    const float* __restrict__ x,
    const float* __restrict__ g1, const float* __restrict__ b1,
    const float* __restrict__ wrep,
    const float* __restrict__ g2, const float* __restrict__ b2, int n)
{
    int t = blockIdx.x * NT + threadIdx.x;
    int node = t >> 5;
    int lane = t & 31;
    if (node >= n) return;

    int tc = g_cnt[node];
    int cnt = tc < MAXDEG ? tc : MAXDEG;
    const int* tp = g_tab + (size_t)node * MAXDEG;
    const char* yb = reinterpret_cast<const char*>(g_y) + lane * 8;

    u64 s0 = 0ULL, s1 = 0ULL, s2 = 0ULL, s3 = 0ULL;
    int e = 0;
    for (; e + 4 <= cnt; e += 4) {
        int i0 = tp[e], i1 = tp[e + 1], i2 = tp[e + 2], i3 = tp[e + 3];
        s0 = add2(s0, *reinterpret_cast<const u64*>(yb + (size_t)i0 * 256));
        s1 = add2(s1, *reinterpret_cast<const u64*>(yb + (size_t)i1 * 256));
        s2 = add2(s2, *reinterpret_cast<const u64*>(yb + (size_t)i2 * 256));
        s3 = add2(s3, *reinterpret_cast<const u64*>(yb + (size_t)i3 * 256));
    }
    for (; e < cnt; e++)
        s0 = add2(s0, *reinterpret_cast<const u64*>(yb + (size_t)tp[e] * 256));
    u64 s = add2(add2(s0, s1), add2(s2, s3));

    float inv = 1.0f / (float)(tc > 1 ? tc : 1);
    s = mul2(s, dup2(inv));

    // LN1 (warp shuffles)
    float p = hsum2(s);
#pragma unroll
    for (int o = 16; o; o >>= 1) p += __shfl_xor_sync(0xffffffffu, p, o);
    float m = p * (1.f / 64.f);
    u64 d = add2(s, dup2(-m));
    float vp = hsum2(mul2(d, d));
#pragma unroll
    for (int o = 16; o; o >>= 1) vp += __shfl_xor_sync(0xffffffffu, vp, o);
    float r = rsqrtf(vp * (1.f / 64.f) + 1e-5f);
    u64 a = fma2(mul2(d, dup2(r)),
                 reinterpret_cast<const u64*>(g1)[lane],
                 reinterpret_cast<const u64*>(b1)[lane]);

    // fx = LN2(x + (x - a)*w)
    u64 xv = *reinterpret_cast<const u64*>(x + (size_t)node * D + lane * 2);
    u64 f = fma2(add2(xv, neg2(a)), reinterpret_cast<const u64*>(wrep)[lane], xv);
    p = hsum2(f);
#pragma unroll
    for (int o = 16; o; o >>= 1) p += __shfl_xor_sync(0xffffffffu, p, o);
    m = p * (1.f / 64.f);
    d = add2(f, dup2(-m));
    vp = hsum2(mul2(d, d));
#pragma unroll
    for (int o = 16; o; o >>= 1) vp += __shfl_xor_sync(0xffffffffu, vp, o);
    r = rsqrtf(vp * (1.f / 64.f) + 1e-5f);
    u64 fx = fma2(mul2(d, dup2(r)),
                  reinterpret_cast<const u64*>(g2)[lane],
                  reinterpret_cast<const u64*>(b2)[lane]);

    // pre-split bf16x2 writes (coalesced)
    float flo, fhi; u32 hp, lp;
    unpack2(fx, flo, fhi);
    split_bf16x2(flo, fhi, hp, lp);
    g_ch[(size_t)node * 64 + lane] = hp;
    g_cl[(size_t)node * 64 + lane] = lp;
    unpack2(a, flo, fhi);
    split_bf16x2(flo, fhi, hp, lp);
    g_ch[(size_t)node * 64 + 32 + lane] = hp;
    g_cl[(size_t)node * 64 + 32 + lane] = lp;
}

// ---------------------------------------------------------------------------
// Epilogue: k-split GEMM1 (fx-half then a-half, accumulating) + GEMM2.
// All staging is pure copies of pre-split data — zero cvt.
// smem 53248 B, 3 CTAs/SM -> ONE wave.
// ---------------------------------------------------------------------------
__global__ __launch_bounds__(NT, 3) void epilogue_kernel(float* __restrict__ out, int n)
{
    extern __shared__ __align__(16) u32 smem[];
    u32* sAh = smem;                     // [32][136]
    u32* sAl = sAh + 32 * CPITCH;
    u32* sWh = sAl + 32 * CPITCH;        // [32][72]
    u32* sWl = sWh + 32 * WPITCH;
    int tid = threadIdx.x;
    int lane = tid & 31, wid = tid >> 5;
    int mb = (wid & 3) * 32, nb = (wid >> 2) * 32;
    int base = blockIdx.x * 128;

    // half 0: fx rows, W2a rows 0..31
    stage_C_copy(0, base, n, sAh, sAl, tid);
    copy_block(g_w2a_h, sWh, 32 * WPITCH, tid);
    copy_block(g_w2a_l, sWl, 32 * WPITCH, tid);
    __syncthreads();

    float Dt[2][4][4];
    mma_gemm<4, true>(sAh, sAl, sWh, sWl, mb, nb, lane, Dt);
    __syncthreads();

    // half 1: a rows, W2a rows 32..63
    stage_C_copy(1, base, n, sAh, sAl, tid);
    copy_block(g_w2a_h + 32 * WPITCH, sWh, 32 * WPITCH, tid);
    copy_block(g_w2a_l + 32 * WPITCH, sWl, 32 * WPITCH, tid);
    __syncthreads();

    mma_gemm<4, false>(sAh, sAl, sWh, sWl, mb, nb, lane, Dt);
    __syncthreads();

    // hidden -> sA; W2b
    relu_split(Dt, sAh, sAl, mb, nb, lane);
    copy_block(g_w2b_h, sWh, 32 * WPITCH, tid);
    copy_block(g_w2b_l, sWl, 32 * WPITCH, tid);
    __syncthreads();

    mma_gemm<4, true>(sAh, sAl, sWh, sWl, mb, nb, lane, Dt);
    store_frag(Dt, out, base, n, mb, nb, lane);
}

// ---------------------------------------------------------------------------
// Launch
// ---------------------------------------------------------------------------
extern "C" void kernel_launch(void* const* d_in, const int* in_sizes, int n_in,
                              void* d_out, int out_size) {
    const float* x   = (const float*)d_in[0];
    const int*   ei  = (const int*)d_in[1];      // int32 (jax downcasts int64)
    const float* W1a = (const float*)d_in[2];
    const float* W1b = (const float*)d_in[3];
    const float* g1  = (const float*)d_in[4];
    const float* b1  = (const float*)d_in[5];
    const float* w   = (const float*)d_in[6];
    const float* g2  = (const float*)d_in[7];
    const float* b2  = (const float*)d_in[8];
    const float* W2a = (const float*)d_in[9];
    const float* W2b = (const float*)d_in[10];
    float* out = (float*)d_out;

    int n = in_sizes[0] / D;
    int E = in_sizes[1] / 2;
    int blocks = (n + 127) / 128;

    const int GEMM_SMEM = (2 * 32 * CPITCH + 2 * 32 * WPITCH) * 4;   // 53248 B
    cudaFuncSetAttribute(mlp1_kernel, cudaFuncAttributeMaxDynamicSharedMemorySize, GEMM_SMEM);
    cudaFuncSetAttribute(epilogue_kernel, cudaFuncAttributeMaxDynamicSharedMemorySize, GEMM_SMEM);

    mlp1_kernel<<<blocks, NT, GEMM_SMEM>>>(x, W1a, W1b, n);
    fill_kernel<<<WBLK + (E + 255) / 256, 256>>>(ei, E, n, W2a, W2b);
    agg_kernel<<<(n * 32 + NT - 1) / NT, NT>>>(x, g1, b1, w, g2, b2, n);
    epilogue_kernel<<<blocks, NT, GEMM_SMEM>>>(out, n);
}